// round 6
// baseline (speedup 1.0000x reference)
#include <cuda_runtime.h>
#include <cuda_fp16.h>
#include <cstdint>

// Problem dims
constexpr int kT  = 8192;
constexpr int kNS = 512;
constexpr int kNH = 1024;
constexpr int kNO = 512;
constexpr int kNG = 4 * kNH;  // 4096 gate rows

constexpr int kNumCTA = 128;                 // persistent CTAs (<148 SMs -> co-resident)
constexpr int kUnitsPerCTA = kNH / kNumCTA;  // 8 hidden units per CTA

// ---------------- scratch (static device allocations; no cudaMalloc) ----------------
__device__ float g_Z[(size_t)kT * kNG];    // 128 MB: gate preactivations / reused for logits
__device__ float g_H0[(size_t)kT * kNH];   // 32 MB
__device__ float g_H1[(size_t)kT * kNH];   // 32 MB
__device__ __align__(16) int g_prog[2][kNumCTA];  // per-CTA monotonic progress, per layer

// ---------------- init ----------------
__global__ void zero_prog_kernel(int* p, int n) {
    int i = blockIdx.x * blockDim.x + threadIdx.x;
    if (i < n) p[i] = 0;
}

// ---------------- fp32 tiled GEMM: C[M,N] = A[M,K] * B[N,K]^T (+bias1[n]+bias2[n]) ----
__global__ __launch_bounds__(256) void gemm_nt(
    const float* __restrict__ A, const float* __restrict__ B,
    const float* __restrict__ b1, const float* __restrict__ b2,
    float* __restrict__ C, int M, int N, int K)
{
    __shared__ float As[8][128];
    __shared__ float Bs[8][128];
    const int tid = threadIdx.x;
    const int m0 = blockIdx.y * 128;
    const int n0 = blockIdx.x * 128;
    const int ty = tid >> 4;          // 0..15
    const int tx = tid & 15;          // 0..15
    const int lrow = tid >> 1;        // 0..127
    const int lk = (tid & 1) * 4;     // 0 or 4
    const float* Ap = A + (size_t)(m0 + lrow) * K + lk;
    const float* Bp = B + (size_t)(n0 + lrow) * K + lk;

    float acc[8][8];
#pragma unroll
    for (int i = 0; i < 8; i++)
#pragma unroll
        for (int j = 0; j < 8; j++) acc[i][j] = 0.f;

    for (int k0 = 0; k0 < K; k0 += 8) {
        float4 av = *(const float4*)(Ap + k0);
        float4 bv = *(const float4*)(Bp + k0);
        As[lk + 0][lrow] = av.x; As[lk + 1][lrow] = av.y;
        As[lk + 2][lrow] = av.z; As[lk + 3][lrow] = av.w;
        Bs[lk + 0][lrow] = bv.x; Bs[lk + 1][lrow] = bv.y;
        Bs[lk + 2][lrow] = bv.z; Bs[lk + 3][lrow] = bv.w;
        __syncthreads();
#pragma unroll
        for (int kk = 0; kk < 8; kk++) {
            float a[8], b[8];
#pragma unroll
            for (int i = 0; i < 8; i++) a[i] = As[kk][i * 16 + ty];
#pragma unroll
            for (int j = 0; j < 8; j++) b[j] = Bs[kk][j * 16 + tx];
#pragma unroll
            for (int i = 0; i < 8; i++)
#pragma unroll
                for (int j = 0; j < 8; j++) acc[i][j] += a[i] * b[j];
        }
        __syncthreads();
    }

#pragma unroll
    for (int j = 0; j < 8; j++) {
        int n = n0 + j * 16 + tx;
        float bias = 0.f;
        if (b1) bias += b1[n];
        if (b2) bias += b2[n];
#pragma unroll
        for (int i = 0; i < 8; i++) {
            int m = m0 + i * 16 + ty;
            C[(size_t)m * N + n] = acc[i][j] + bias;
        }
    }
}

// ---------------- persistent LSTM recurrence (fp16 weights, fp32 accumulate) ------
// Z: [T, 4096] precomputed x-projection WITH biases already added.
// Whh: [4096, 1024] row-major fp32 (torch gate order i,f,g,o) -> fp16 in SMEM.
// H:  [T, 1024] output hidden states (fp32).
// prog: per-CTA monotonic progress flags (zeroed before launch). prog[b] = t+1
//       means CTA b has published H[t]. Spread addresses -> no L2 slice hotspot.
// Each CTA b owns hidden units b*8 .. b*8+7 (32 gate rows) held in SMEM as half2.
__global__ __launch_bounds__(256) void lstm_rec(
    const float* __restrict__ Z, const float* __restrict__ Whh,
    float* H, int* prog)
{
    extern __shared__ __half2 sW[];          // [32][512] half2 = 64 KB
    __shared__ float sH[kNH];                // staged h[t-1] (4 KB)
    __shared__ float sDot[2][32];            // double-buffered gate dots

    const int tid  = threadIdx.x;
    const int b    = blockIdx.x;
    const int warp = tid >> 5;
    const int lane = tid & 31;

    // ---- load + convert this CTA's 32 weight rows (gate-major lr = g*8+u) ----
    for (int i = tid; i < 32 * 512; i += 256) {
        int lr = i >> 9, p = i & 511;
        int g = lr >> 3, u = lr & 7;
        const float2 wv = *(const float2*)(
            Whh + (size_t)(g * kNH + b * kUnitsPerCTA + u) * kNH + 2 * p);
        sW[i] = __floats2half2_rn(wv.x, wv.y);
    }
    // zero sH for t = 0
    {
        float4 z4 = make_float4(0.f, 0.f, 0.f, 0.f);
        ((float4*)sH)[tid] = z4;
    }
    __syncthreads();

    const __half2* wbase = sW + (size_t)(warp * 4) * 512;  // this warp's 4 rows
    float creg = 0.f;                                      // cell state (warp0 lanes 0..7)
    const int4* prog4 = (const int4*)prog;

    for (int t = 0; t < kT; t++) {
        // ---- prefetch Z[t] contribution (warp 0) — issued before the poll ----
        float zv = 0.f;
        if (warp == 0) {
            zv = Z[(size_t)t * kNG + (lane >> 3) * kNH + b * kUnitsPerCTA + (lane & 7)];
        }

        if (t > 0) {
            // ---- acquire: wait until all 128 CTAs have published H[t-1] ----
            // each lane acquires 4 spread flags; no single-address hotspot.
            bool ok;
            do {
                int4 v;
                asm volatile("ld.acquire.gpu.global.v4.u32 {%0,%1,%2,%3}, [%4];"
                             : "=r"(v.x), "=r"(v.y), "=r"(v.z), "=r"(v.w)
                             : "l"(prog4 + lane) : "memory");
                ok = (v.x >= t) & (v.y >= t) & (v.z >= t) & (v.w >= t);
            } while (!__all_sync(0xffffffffu, ok));
            // ---- stage h[t-1] into SMEM once per CTA (256 x float4 = 4 KB) ----
            float4 hv = __ldcg((const float4*)(H + (size_t)(t - 1) * kNH) + tid);
            ((float4*)sH)[tid] = hv;
        }
        __syncthreads();   // sH ready; also fences sDot[t&1] writes below vs prior reads

        // ---- matvec: each warp computes 4 gate rows, fp16 weights, fp32 acc ----
        float2 h2[16];
        const float2* sHp = (const float2*)sH;
#pragma unroll
        for (int j = 0; j < 16; j++) h2[j] = sHp[j * 32 + lane];

        float s0 = 0.f, s1 = 0.f, s2 = 0.f, s3 = 0.f;
#pragma unroll
        for (int j = 0; j < 16; j++) {
            const int idx = j * 32 + lane;
            float2 w0 = __half22float2(wbase[idx]);
            float2 w1 = __half22float2(wbase[512 + idx]);
            float2 w2 = __half22float2(wbase[1024 + idx]);
            float2 w3 = __half22float2(wbase[1536 + idx]);
            s0 = fmaf(w0.x, h2[j].x, fmaf(w0.y, h2[j].y, s0));
            s1 = fmaf(w1.x, h2[j].x, fmaf(w1.y, h2[j].y, s1));
            s2 = fmaf(w2.x, h2[j].x, fmaf(w2.y, h2[j].y, s2));
            s3 = fmaf(w3.x, h2[j].x, fmaf(w3.y, h2[j].y, s3));
        }
#pragma unroll
        for (int off = 16; off; off >>= 1) {
            s0 += __shfl_xor_sync(0xffffffffu, s0, off);
            s1 += __shfl_xor_sync(0xffffffffu, s1, off);
            s2 += __shfl_xor_sync(0xffffffffu, s2, off);
            s3 += __shfl_xor_sync(0xffffffffu, s3, off);
        }
        if (lane == 0) {
            float* d = &sDot[t & 1][warp * 4];
            d[0] = s0; d[1] = s1; d[2] = s2; d[3] = s3;
        }
        __syncthreads();  // sDot[t&1] complete; all sH reads for step t done

        // ---- activation + state update: warp 0 only; other warps race to poll t+1
        if (warp == 0) {
            float z = sDot[t & 1][lane] + zv;
            // sigmoid gates -> sig(z); g gate -> tanh(z) = 2*sig(2z)-1
            const bool isg = (lane >= 16) & (lane < 24);
            const float sm = isg ? 2.f : 1.f;
            float sig = 1.f / (1.f + __expf(-sm * z));
            float a = isg ? fmaf(sig, 2.f, -1.f) : sig;
            const int u = lane & 7;
            float i_ = __shfl_sync(0xffffffffu, a, u);
            float f_ = __shfl_sync(0xffffffffu, a, 8 + u);
            float g_ = __shfl_sync(0xffffffffu, a, 16 + u);
            float o_ = __shfl_sync(0xffffffffu, a, 24 + u);
            if (lane < kUnitsPerCTA) {
                creg = fmaf(f_, creg, i_ * g_);
                float tc = 2.f / (1.f + __expf(-2.f * creg)) - 1.f;
                H[(size_t)t * kNH + b * kUnitsPerCTA + lane] = o_ * tc;
            }
            __syncwarp();  // H writes (lanes 0..7) ordered before lane 0's release
            if (lane == 0) {
                int nv = t + 1;
                asm volatile("st.release.gpu.global.u32 [%0], %1;"
                             :: "l"(prog + b), "r"(nv) : "memory");
            }
        }
        // no trailing barrier: sDot double-buffered; sH(t+1) writes can only happen
        // after this CTA's own flag reaches t+1 (own-flag poll), i.e. after release.
    }
}

// ---------------- softmax over NO=512 per row ----------------
__global__ __launch_bounds__(256) void softmax_rows(
    const float* __restrict__ L, float* __restrict__ out)
{
    __shared__ float red[256];
    int t = blockIdx.x, tid = threadIdx.x;
    const float* row = L + (size_t)t * kNO;
    float v0 = row[tid], v1 = row[tid + 256];
    float m = fmaxf(v0, v1);
    red[tid] = m; __syncthreads();
    for (int s = 128; s; s >>= 1) {
        if (tid < s) red[tid] = fmaxf(red[tid], red[tid + s]);
        __syncthreads();
    }
    m = red[0]; __syncthreads();
    float e0 = expf(v0 - m), e1 = expf(v1 - m);
    red[tid] = e0 + e1; __syncthreads();
    for (int s = 128; s; s >>= 1) {
        if (tid < s) red[tid] += red[tid + s];
        __syncthreads();
    }
    float inv = 1.f / red[0];
    out[(size_t)t * kNO + tid]       = e0 * inv;
    out[(size_t)t * kNO + tid + 256] = e1 * inv;
}

// ---------------- value head: out[t] = H1[t] . w_val + b_val ----------------
__global__ __launch_bounds__(256) void value_head(
    const float* __restrict__ H1, const float* __restrict__ wv,
    const float* __restrict__ bv, float* __restrict__ out)
{
    __shared__ float red[256];
    int t = blockIdx.x, tid = threadIdx.x;
    const float* h = H1 + (size_t)t * kNH;
    float s = 0.f;
    for (int k = tid; k < kNH; k += 256) s += h[k] * wv[k];
    red[tid] = s; __syncthreads();
    for (int r = 128; r; r >>= 1) {
        if (tid < r) red[tid] += red[tid + r];
        __syncthreads();
    }
    if (tid == 0) out[t] = red[0] + bv[0];
}

// ---------------- launch ----------------
extern "C" void kernel_launch(void* const* d_in, const int* in_sizes, int n_in,
                              void* d_out, int out_size)
{
    (void)in_sizes; (void)n_in; (void)out_size;
    const float* x     = (const float*)d_in[0];
    const float* w_ih0 = (const float*)d_in[1];
    const float* w_hh0 = (const float*)d_in[2];
    const float* b_ih0 = (const float*)d_in[3];
    const float* b_hh0 = (const float*)d_in[4];
    const float* w_ih1 = (const float*)d_in[5];
    const float* w_hh1 = (const float*)d_in[6];
    const float* b_ih1 = (const float*)d_in[7];
    const float* b_hh1 = (const float*)d_in[8];
    const float* w_pol = (const float*)d_in[9];
    const float* b_pol = (const float*)d_in[10];
    const float* w_val = (const float*)d_in[11];
    const float* b_val = (const float*)d_in[12];
    float* out = (float*)d_out;

    float *Z, *H0, *H1;
    int* prog;
    cudaGetSymbolAddress((void**)&Z, g_Z);
    cudaGetSymbolAddress((void**)&H0, g_H0);
    cudaGetSymbolAddress((void**)&H1, g_H1);
    cudaGetSymbolAddress((void**)&prog, g_prog);

    const int smem = 32 * 512 * (int)sizeof(__half2);  // 64 KB dynamic (weights)
    cudaFuncSetAttribute(lstm_rec, cudaFuncAttributeMaxDynamicSharedMemorySize, smem);

    // reset progress flags every launch (replay-deterministic)
    zero_prog_kernel<<<1, 256>>>(prog, 2 * kNumCTA);

    // Z0 = X @ w_ih0^T + (b_ih0 + b_hh0)
    gemm_nt<<<dim3(kNG / 128, kT / 128), 256>>>(x, w_ih0, b_ih0, b_hh0, Z, kT, kNG, kNS);
    // layer-0 recurrence -> H0
    lstm_rec<<<kNumCTA, 256, smem>>>(Z, w_hh0, H0, prog);
    // Z1 = H0 @ w_ih1^T + (b_ih1 + b_hh1)
    gemm_nt<<<dim3(kNG / 128, kT / 128), 256>>>(H0, w_ih1, b_ih1, b_hh1, Z, kT, kNG, kNH);
    // layer-1 recurrence -> H1
    lstm_rec<<<kNumCTA, 256, smem>>>(Z, w_hh1, H1, prog + kNumCTA);
    // policy logits = H1 @ w_pol^T + b_pol (into Z scratch)
    gemm_nt<<<dim3(kNO / 128, kT / 128), 256>>>(H1, w_pol, b_pol, nullptr, Z, kT, kNO, kNH);
    // softmax -> out[0 : T*NO)
    softmax_rows<<<kT, 256>>>(Z, out);
    // value -> out[T*NO : T*NO + T)
    value_head<<<kT, 256>>>(H1, w_val, b_val, out + (size_t)kT * kNO);
}

// round 8
// speedup vs baseline: 2.9323x; 2.9323x over previous
#include <cuda_runtime.h>
#include <cuda_fp16.h>
#include <cstdint>

// Problem dims
constexpr int kT  = 8192;
constexpr int kNS = 512;
constexpr int kNH = 1024;
constexpr int kNO = 512;
constexpr int kNG = 4 * kNH;  // 4096 gate rows

constexpr int kNumCTA = 128;                 // persistent CTAs (<148 SMs -> co-resident)
constexpr int kUnitsPerCTA = kNH / kNumCTA;  // 8 hidden units per CTA
constexpr int kFlagStride = 64;              // ints: 256 B between flags -> many L2 slices

// ---------------- scratch (static device allocations; no cudaMalloc) ----------------
__device__ float g_Z[(size_t)kT * kNG];    // 128 MB: gate preactivations / reused for logits
__device__ float g_H0[(size_t)kT * kNH];   // 32 MB
__device__ float g_H1[(size_t)kT * kNH];   // 32 MB
__device__ int   g_prog[2 * kNumCTA * kFlagStride];  // padded per-CTA progress flags

// ---------------- init ----------------
__global__ void zero_prog_kernel(int* p, int n) {
    int i = blockIdx.x * blockDim.x + threadIdx.x;
    if (i < n) p[i] = 0;
}

// ---------------- fp32 tiled GEMM: C[M,N] = A[M,K] * B[N,K]^T (+bias1[n]+bias2[n]) ----
__global__ __launch_bounds__(256) void gemm_nt(
    const float* __restrict__ A, const float* __restrict__ B,
    const float* __restrict__ b1, const float* __restrict__ b2,
    float* __restrict__ C, int M, int N, int K)
{
    __shared__ float As[8][128];
    __shared__ float Bs[8][128];
    const int tid = threadIdx.x;
    const int m0 = blockIdx.y * 128;
    const int n0 = blockIdx.x * 128;
    const int ty = tid >> 4;          // 0..15
    const int tx = tid & 15;          // 0..15
    const int lrow = tid >> 1;        // 0..127
    const int lk = (tid & 1) * 4;     // 0 or 4
    const float* Ap = A + (size_t)(m0 + lrow) * K + lk;
    const float* Bp = B + (size_t)(n0 + lrow) * K + lk;

    float acc[8][8];
#pragma unroll
    for (int i = 0; i < 8; i++)
#pragma unroll
        for (int j = 0; j < 8; j++) acc[i][j] = 0.f;

    for (int k0 = 0; k0 < K; k0 += 8) {
        float4 av = *(const float4*)(Ap + k0);
        float4 bv = *(const float4*)(Bp + k0);
        As[lk + 0][lrow] = av.x; As[lk + 1][lrow] = av.y;
        As[lk + 2][lrow] = av.z; As[lk + 3][lrow] = av.w;
        Bs[lk + 0][lrow] = bv.x; Bs[lk + 1][lrow] = bv.y;
        Bs[lk + 2][lrow] = bv.z; Bs[lk + 3][lrow] = bv.w;
        __syncthreads();
#pragma unroll
        for (int kk = 0; kk < 8; kk++) {
            float a[8], b[8];
#pragma unroll
            for (int i = 0; i < 8; i++) a[i] = As[kk][i * 16 + ty];
#pragma unroll
            for (int j = 0; j < 8; j++) b[j] = Bs[kk][j * 16 + tx];
#pragma unroll
            for (int i = 0; i < 8; i++)
#pragma unroll
                for (int j = 0; j < 8; j++) acc[i][j] += a[i] * b[j];
        }
        __syncthreads();
    }

#pragma unroll
    for (int j = 0; j < 8; j++) {
        int n = n0 + j * 16 + tx;
        float bias = 0.f;
        if (b1) bias += b1[n];
        if (b2) bias += b2[n];
#pragma unroll
        for (int i = 0; i < 8; i++) {
            int m = m0 + i * 16 + ty;
            C[(size_t)m * N + n] = acc[i][j] + bias;
        }
    }
}

// ---------------- persistent LSTM recurrence (fp16 weights, fp32 accumulate) ------
// Z: [T, 4096] precomputed x-projection WITH biases already added.
// Whh: [4096, 1024] row-major fp32 (torch gate order i,f,g,o) -> fp16 in SMEM.
// H:  [T, 1024] output hidden states (fp32).
// prog: padded per-CTA progress flags (stride 256 B). prog[b*64] = t+1 means CTA b
//       published H[t]. Only warp 0 polls; __syncthreads broadcasts.
// Each CTA b owns hidden units b*8 .. b*8+7 (32 gate rows) in SMEM as half2.
__global__ __launch_bounds__(256) void lstm_rec(
    const float* __restrict__ Z, const float* __restrict__ Whh,
    float* H, int* prog)
{
    extern __shared__ __half2 sW[];          // [32][512] half2 = 64 KB
    __shared__ float sH[kNH];                // staged h[t-1] (4 KB)
    __shared__ float sDot[2][32];            // double-buffered gate dots

    const int tid  = threadIdx.x;
    const int b    = blockIdx.x;
    const int warp = tid >> 5;
    const int lane = tid & 31;

    // ---- load + convert this CTA's 32 weight rows (gate-major lr = g*8+u) ----
    for (int i = tid; i < 32 * 512; i += 256) {
        int lr = i >> 9, p = i & 511;
        int g = lr >> 3, u = lr & 7;
        const float2 wv = *(const float2*)(
            Whh + (size_t)(g * kNH + b * kUnitsPerCTA + u) * kNH + 2 * p);
        sW[i] = __floats2half2_rn(wv.x, wv.y);
    }
    // zero sH for t = 0
    ((float4*)sH)[tid] = make_float4(0.f, 0.f, 0.f, 0.f);
    __syncthreads();

    const __half2* wbase = sW + (size_t)(warp * 4) * 512;  // this warp's 4 rows
    float creg = 0.f;                                      // cell state (warp0 lanes 0..7)
    // warp-0 poll addresses: lane polls flags lane*4 .. lane*4+3 (each 256 B apart)
    const int* f0 = prog + (lane * 4 + 0) * kFlagStride;
    const int* f1 = prog + (lane * 4 + 1) * kFlagStride;
    const int* f2 = prog + (lane * 4 + 2) * kFlagStride;
    const int* f3 = prog + (lane * 4 + 3) * kFlagStride;

    for (int t = 0; t < kT; t++) {
        // ---- prefetch Z[t] contribution (warp 0) — issued before the poll ----
        float zv = 0.f;
        if (warp == 0) {
            zv = Z[(size_t)t * kNG + (lane >> 3) * kNH + b * kUnitsPerCTA + (lane & 7)];
        }

        if (t > 0) {
            // ---- acquire: warp 0 waits until all 128 CTAs published H[t-1] ----
            if (warp == 0) {
                bool ok;
                do {
                    int a0, a1, a2, a3;
                    asm volatile("ld.acquire.gpu.global.u32 %0, [%1];" : "=r"(a0) : "l"(f0) : "memory");
                    asm volatile("ld.acquire.gpu.global.u32 %0, [%1];" : "=r"(a1) : "l"(f1) : "memory");
                    asm volatile("ld.acquire.gpu.global.u32 %0, [%1];" : "=r"(a2) : "l"(f2) : "memory");
                    asm volatile("ld.acquire.gpu.global.u32 %0, [%1];" : "=r"(a3) : "l"(f3) : "memory");
                    ok = (a0 >= t) & (a1 >= t) & (a2 >= t) & (a3 >= t);
                } while (!__all_sync(0xffffffffu, ok));
            }
            __syncthreads();   // broadcast "H[t-1] ready" to whole CTA
            // ---- stage h[t-1] into SMEM once per CTA (256 x float4 = 4 KB) ----
            ((float4*)sH)[tid] = __ldcg((const float4*)(H + (size_t)(t - 1) * kNH) + tid);
            __syncthreads();   // sH ready
        }

        // ---- matvec: each warp computes 4 gate rows, fp16 weights, fp32 acc ----
        float2 h2[16];
        const float2* sHp = (const float2*)sH;
#pragma unroll
        for (int j = 0; j < 16; j++) h2[j] = sHp[j * 32 + lane];

        float s0 = 0.f, s1 = 0.f, s2 = 0.f, s3 = 0.f;
#pragma unroll
        for (int j = 0; j < 16; j++) {
            const int idx = j * 32 + lane;
            float2 w0 = __half22float2(wbase[idx]);
            float2 w1 = __half22float2(wbase[512 + idx]);
            float2 w2 = __half22float2(wbase[1024 + idx]);
            float2 w3 = __half22float2(wbase[1536 + idx]);
            s0 = fmaf(w0.x, h2[j].x, fmaf(w0.y, h2[j].y, s0));
            s1 = fmaf(w1.x, h2[j].x, fmaf(w1.y, h2[j].y, s1));
            s2 = fmaf(w2.x, h2[j].x, fmaf(w2.y, h2[j].y, s2));
            s3 = fmaf(w3.x, h2[j].x, fmaf(w3.y, h2[j].y, s3));
        }
#pragma unroll
        for (int off = 16; off; off >>= 1) {
            s0 += __shfl_xor_sync(0xffffffffu, s0, off);
            s1 += __shfl_xor_sync(0xffffffffu, s1, off);
            s2 += __shfl_xor_sync(0xffffffffu, s2, off);
            s3 += __shfl_xor_sync(0xffffffffu, s3, off);
        }
        if (lane == 0) {
            float* d = &sDot[t & 1][warp * 4];
            d[0] = s0; d[1] = s1; d[2] = s2; d[3] = s3;
        }
        __syncthreads();  // sDot[t&1] complete

        // ---- activation + state update: warp 0 only; others go wait at next barrier
        if (warp == 0) {
            float z = sDot[t & 1][lane] + zv;
            // sigmoid gates -> sig(z); g gate -> tanh(z) = 2*sig(2z)-1
            const bool isg = (lane >= 16) & (lane < 24);
            const float sm = isg ? 2.f : 1.f;
            float sig = 1.f / (1.f + __expf(-sm * z));
            float a = isg ? fmaf(sig, 2.f, -1.f) : sig;
            const int u = lane & 7;
            float i_ = __shfl_sync(0xffffffffu, a, u);
            float f_ = __shfl_sync(0xffffffffu, a, 8 + u);
            float g_ = __shfl_sync(0xffffffffu, a, 16 + u);
            float o_ = __shfl_sync(0xffffffffu, a, 24 + u);
            if (lane < kUnitsPerCTA) {
                creg = fmaf(f_, creg, i_ * g_);
                float tc = 2.f / (1.f + __expf(-2.f * creg)) - 1.f;
                H[(size_t)t * kNH + b * kUnitsPerCTA + lane] = o_ * tc;
            }
            __syncwarp();  // H writes (lanes 0..7) ordered before lane 0's release
            if (lane == 0) {
                int nv = t + 1;
                asm volatile("st.release.gpu.global.u32 [%0], %1;"
                             :: "l"(prog + b * kFlagStride), "r"(nv) : "memory");
            }
        }
        // no trailing barrier: only warp 0 polls, and it is the warp that did the
        // release; other warps block at the next __syncthreads until warp 0 passes
        // its poll, so no sH/sDot hazards are possible.
    }
}

// ---------------- softmax over NO=512 per row ----------------
__global__ __launch_bounds__(256) void softmax_rows(
    const float* __restrict__ L, float* __restrict__ out)
{
    __shared__ float red[256];
    int t = blockIdx.x, tid = threadIdx.x;
    const float* row = L + (size_t)t * kNO;
    float v0 = row[tid], v1 = row[tid + 256];
    float m = fmaxf(v0, v1);
    red[tid] = m; __syncthreads();
    for (int s = 128; s; s >>= 1) {
        if (tid < s) red[tid] = fmaxf(red[tid], red[tid + s]);
        __syncthreads();
    }
    m = red[0]; __syncthreads();
    float e0 = expf(v0 - m), e1 = expf(v1 - m);
    red[tid] = e0 + e1; __syncthreads();
    for (int s = 128; s; s >>= 1) {
        if (tid < s) red[tid] += red[tid + s];
        __syncthreads();
    }
    float inv = 1.f / red[0];
    out[(size_t)t * kNO + tid]       = e0 * inv;
    out[(size_t)t * kNO + tid + 256] = e1 * inv;
}

// ---------------- value head: out[t] = H1[t] . w_val + b_val ----------------
__global__ __launch_bounds__(256) void value_head(
    const float* __restrict__ H1, const float* __restrict__ wv,
    const float* __restrict__ bv, float* __restrict__ out)
{
    __shared__ float red[256];
    int t = blockIdx.x, tid = threadIdx.x;
    const float* h = H1 + (size_t)t * kNH;
    float s = 0.f;
    for (int k = tid; k < kNH; k += 256) s += h[k] * wv[k];
    red[tid] = s; __syncthreads();
    for (int r = 128; r; r >>= 1) {
        if (tid < r) red[tid] += red[tid + r];
        __syncthreads();
    }
    if (tid == 0) out[t] = red[0] + bv[0];
}

// ---------------- launch ----------------
extern "C" void kernel_launch(void* const* d_in, const int* in_sizes, int n_in,
                              void* d_out, int out_size)
{
    (void)in_sizes; (void)n_in; (void)out_size;
    const float* x     = (const float*)d_in[0];
    const float* w_ih0 = (const float*)d_in[1];
    const float* w_hh0 = (const float*)d_in[2];
    const float* b_ih0 = (const float*)d_in[3];
    const float* b_hh0 = (const float*)d_in[4];
    const float* w_ih1 = (const float*)d_in[5];
    const float* w_hh1 = (const float*)d_in[6];
    const float* b_ih1 = (const float*)d_in[7];
    const float* b_hh1 = (const float*)d_in[8];
    const float* w_pol = (const float*)d_in[9];
    const float* b_pol = (const float*)d_in[10];
    const float* w_val = (const float*)d_in[11];
    const float* b_val = (const float*)d_in[12];
    float* out = (float*)d_out;

    float *Z, *H0, *H1;
    int* prog;
    cudaGetSymbolAddress((void**)&Z, g_Z);
    cudaGetSymbolAddress((void**)&H0, g_H0);
    cudaGetSymbolAddress((void**)&H1, g_H1);
    cudaGetSymbolAddress((void**)&prog, g_prog);

    const int smem = 32 * 512 * (int)sizeof(__half2);  // 64 KB dynamic (weights)
    cudaFuncSetAttribute(lstm_rec, cudaFuncAttributeMaxDynamicSharedMemorySize, smem);

    // reset progress flags every launch (replay-deterministic)
    zero_prog_kernel<<<(2 * kNumCTA * kFlagStride + 255) / 256, 256>>>(
        prog, 2 * kNumCTA * kFlagStride);

    // Z0 = X @ w_ih0^T + (b_ih0 + b_hh0)
    gemm_nt<<<dim3(kNG / 128, kT / 128), 256>>>(x, w_ih0, b_ih0, b_hh0, Z, kT, kNG, kNS);
    // layer-0 recurrence -> H0
    lstm_rec<<<kNumCTA, 256, smem>>>(Z, w_hh0, H0, prog);
    // Z1 = H0 @ w_ih1^T + (b_ih1 + b_hh1)
    gemm_nt<<<dim3(kNG / 128, kT / 128), 256>>>(H0, w_ih1, b_ih1, b_hh1, Z, kT, kNG, kNH);
    // layer-1 recurrence -> H1
    lstm_rec<<<kNumCTA, 256, smem>>>(Z, w_hh1, H1, prog + kNumCTA * kFlagStride);
    // policy logits = H1 @ w_pol^T + b_pol (into Z scratch)
    gemm_nt<<<dim3(kNO / 128, kT / 128), 256>>>(H1, w_pol, b_pol, nullptr, Z, kT, kNO, kNH);
    // softmax -> out[0 : T*NO)
    softmax_rows<<<kT, 256>>>(Z, out);
    // value -> out[T*NO : T*NO + T)
    value_head<<<kT, 256>>>(H1, w_val, b_val, out + (size_t)kT * kNO);
}

// round 10
// speedup vs baseline: 4.9106x; 1.6747x over previous
#include <cuda_runtime.h>
#include <cuda_fp16.h>
#include <cstdint>

// Problem dims
constexpr int kT  = 8192;
constexpr int kNS = 512;
constexpr int kNH = 1024;
constexpr int kNO = 512;
constexpr int kNG = 4 * kNH;  // 4096 gate rows

constexpr int kNumCTA = 128;                 // persistent CTAs (<148 SMs -> co-resident)
constexpr int kUnitsPerCTA = kNH / kNumCTA;  // 8 hidden units per CTA
constexpr int kFlagStride = 64;              // ints: 256 B between flags

// ---------------- scratch (static device allocations; no cudaMalloc) ----------------
__device__ float g_Z[(size_t)kT * kNG];    // 128 MB: layer-0 gate preactivations / logits
__device__ float g_H0[(size_t)kT * kNH];   // 32 MB
__device__ float g_H1[(size_t)kT * kNH];   // 32 MB
__device__ int   g_prog[2 * kNumCTA * kFlagStride];  // prog0 | prog1 (padded flags)

// ---------------- init ----------------
__global__ void zero_prog_kernel(int* p, int n) {
    int i = blockIdx.x * blockDim.x + threadIdx.x;
    if (i < n) p[i] = 0;
}

// ---------------- fp32 tiled GEMM: C[M,N] = A[M,K] * B[N,K]^T (+bias1[n]+bias2[n]) ----
__global__ __launch_bounds__(256) void gemm_nt(
    const float* __restrict__ A, const float* __restrict__ B,
    const float* __restrict__ b1, const float* __restrict__ b2,
    float* __restrict__ C, int M, int N, int K)
{
    __shared__ float As[8][128];
    __shared__ float Bs[8][128];
    const int tid = threadIdx.x;
    const int m0 = blockIdx.y * 128;
    const int n0 = blockIdx.x * 128;
    const int ty = tid >> 4;
    const int tx = tid & 15;
    const int lrow = tid >> 1;
    const int lk = (tid & 1) * 4;
    const float* Ap = A + (size_t)(m0 + lrow) * K + lk;
    const float* Bp = B + (size_t)(n0 + lrow) * K + lk;

    float acc[8][8];
#pragma unroll
    for (int i = 0; i < 8; i++)
#pragma unroll
        for (int j = 0; j < 8; j++) acc[i][j] = 0.f;

    for (int k0 = 0; k0 < K; k0 += 8) {
        float4 av = *(const float4*)(Ap + k0);
        float4 bv = *(const float4*)(Bp + k0);
        As[lk + 0][lrow] = av.x; As[lk + 1][lrow] = av.y;
        As[lk + 2][lrow] = av.z; As[lk + 3][lrow] = av.w;
        Bs[lk + 0][lrow] = bv.x; Bs[lk + 1][lrow] = bv.y;
        Bs[lk + 2][lrow] = bv.z; Bs[lk + 3][lrow] = bv.w;
        __syncthreads();
#pragma unroll
        for (int kk = 0; kk < 8; kk++) {
            float a[8], b[8];
#pragma unroll
            for (int i = 0; i < 8; i++) a[i] = As[kk][i * 16 + ty];
#pragma unroll
            for (int j = 0; j < 8; j++) b[j] = Bs[kk][j * 16 + tx];
#pragma unroll
            for (int i = 0; i < 8; i++)
#pragma unroll
                for (int j = 0; j < 8; j++) acc[i][j] += a[i] * b[j];
        }
        __syncthreads();
    }

#pragma unroll
    for (int j = 0; j < 8; j++) {
        int n = n0 + j * 16 + tx;
        float bias = 0.f;
        if (b1) bias += b1[n];
        if (b2) bias += b2[n];
#pragma unroll
        for (int i = 0; i < 8; i++) {
            int m = m0 + i * 16 + ty;
            C[(size_t)m * N + n] = acc[i][j] + bias;
        }
    }
}

// ---------------- fused 2-layer persistent LSTM recurrence -------------------------
// Two independent warp groups per CTA (512 threads):
//   group A (warps 0-7):  layer-0.  h0[e] = cell(Z0[e], W_hh0 @ h0[e-1])
//   group B (warps 8-15): layer-1.  h1[e] = cell(W_ih1 @ h0[e] + W_hh1 @ h1[e-1] + b1)
// Groups share SMEM weights but synchronize ONLY via named barriers within their own
// group and global prog0/prog1 flags across CTAs. Layer-1 lags layer-0 by one epoch
// and runs in its latency shadow -> grid critical path = 8192 epochs, not 16384.
__global__ __launch_bounds__(512) void lstm_fused(
    const float* __restrict__ Z0, const float* __restrict__ Whh0,
    const float* __restrict__ Wih1, const float* __restrict__ Whh1,
    const float* __restrict__ b_ih1, const float* __restrict__ b_hh1,
    float* H0, float* H1, int* prog0, int* prog1)
{
    extern __shared__ __half2 sWdyn[];           // 3 x [32][512] half2 = 192 KB
    __half2* sW0  = sWdyn;                       // W_hh0 rows (group A)
    __half2* sW1i = sWdyn + 32 * 512;            // W_ih1 rows (group B)
    __half2* sW1h = sWdyn + 2 * 32 * 512;        // W_hh1 rows (group B)
    __shared__ float sH0a[kNH];                  // A: staged h0[e-1]
    __shared__ float sH0b[kNH];                  // B: staged h0[e]
    __shared__ float sH1b[kNH];                  // B: staged h1[e-1]
    __shared__ float sDotA[2][32];
    __shared__ float sDotB[2][32];
    __shared__ float sBias1[32];

    const int tid  = threadIdx.x;
    const int b    = blockIdx.x;
    const int warp = tid >> 5;
    const int lane = tid & 31;

    // ---- load + convert weights (gate-major lr = g*8+u), all 512 threads ----
    for (int i = tid; i < 32 * 512; i += 512) {
        int lr = i >> 9, p = i & 511;
        int g = lr >> 3, u = lr & 7;
        size_t row = (size_t)(g * kNH + b * kUnitsPerCTA + u) * kNH + 2 * p;
        float2 w0 = *(const float2*)(Whh0 + row);
        float2 w1 = *(const float2*)(Wih1 + row);
        float2 w2 = *(const float2*)(Whh1 + row);
        sW0[i]  = __floats2half2_rn(w0.x, w0.y);
        sW1i[i] = __floats2half2_rn(w1.x, w1.y);
        sW1h[i] = __floats2half2_rn(w2.x, w2.y);
    }
    if (tid < 32) {
        int g = tid >> 3, u = tid & 7;
        int idx = g * kNH + b * kUnitsPerCTA + u;
        sBias1[tid] = b_ih1[idx] + b_hh1[idx];
    }
    if (tid < 256) {
        ((float4*)sH0a)[tid] = make_float4(0.f, 0.f, 0.f, 0.f);
        ((float4*)sH1b)[tid] = make_float4(0.f, 0.f, 0.f, 0.f);
    }
    __syncthreads();   // last whole-CTA barrier; groups are independent after this

    if (warp < 8) {
        // ================= group A: layer 0 =================
        const __half2* wbase = sW0 + (size_t)(warp * 4) * 512;
        float creg = 0.f;
        const int* f0 = prog0 + (lane * 4 + 0) * kFlagStride;
        const int* f1 = prog0 + (lane * 4 + 1) * kFlagStride;
        const int* f2 = prog0 + (lane * 4 + 2) * kFlagStride;
        const int* f3 = prog0 + (lane * 4 + 3) * kFlagStride;

        for (int e = 0; e < kT; e++) {
            float zv = 0.f;
            if (warp == 0)
                zv = Z0[(size_t)e * kNG + (lane >> 3) * kNH + b * kUnitsPerCTA + (lane & 7)];

            if (e > 0) {
                if (warp == 0) {
                    bool ok;
                    do {
                        int a0, a1, a2, a3;
                        asm volatile("ld.acquire.gpu.global.u32 %0, [%1];" : "=r"(a0) : "l"(f0) : "memory");
                        asm volatile("ld.acquire.gpu.global.u32 %0, [%1];" : "=r"(a1) : "l"(f1) : "memory");
                        asm volatile("ld.acquire.gpu.global.u32 %0, [%1];" : "=r"(a2) : "l"(f2) : "memory");
                        asm volatile("ld.acquire.gpu.global.u32 %0, [%1];" : "=r"(a3) : "l"(f3) : "memory");
                        ok = (a0 >= e) & (a1 >= e) & (a2 >= e) & (a3 >= e);
                    } while (!__all_sync(0xffffffffu, ok));
                }
                asm volatile("bar.sync 1, 256;" ::: "memory");
                ((float4*)sH0a)[tid] = __ldcg((const float4*)(H0 + (size_t)(e - 1) * kNH) + tid);
                asm volatile("bar.sync 1, 256;" ::: "memory");
            }

            // matvec: 4 rows/warp over sH0a
            const float2* sHp = (const float2*)sH0a;
            float s0 = 0.f, s1 = 0.f, s2 = 0.f, s3 = 0.f;
#pragma unroll
            for (int j = 0; j < 16; j++) {
                const int idx = j * 32 + lane;
                float2 hv = sHp[idx];
                float2 w0 = __half22float2(wbase[idx]);
                float2 w1 = __half22float2(wbase[512 + idx]);
                float2 w2 = __half22float2(wbase[1024 + idx]);
                float2 w3 = __half22float2(wbase[1536 + idx]);
                s0 = fmaf(w0.x, hv.x, fmaf(w0.y, hv.y, s0));
                s1 = fmaf(w1.x, hv.x, fmaf(w1.y, hv.y, s1));
                s2 = fmaf(w2.x, hv.x, fmaf(w2.y, hv.y, s2));
                s3 = fmaf(w3.x, hv.x, fmaf(w3.y, hv.y, s3));
            }
#pragma unroll
            for (int off = 16; off; off >>= 1) {
                s0 += __shfl_xor_sync(0xffffffffu, s0, off);
                s1 += __shfl_xor_sync(0xffffffffu, s1, off);
                s2 += __shfl_xor_sync(0xffffffffu, s2, off);
                s3 += __shfl_xor_sync(0xffffffffu, s3, off);
            }
            if (lane == 0) {
                float* d = &sDotA[e & 1][warp * 4];
                d[0] = s0; d[1] = s1; d[2] = s2; d[3] = s3;
            }
            asm volatile("bar.sync 1, 256;" ::: "memory");

            if (warp == 0) {
                float z = sDotA[e & 1][lane] + zv;
                const bool isg = (lane >= 16) & (lane < 24);
                const float sm = isg ? 2.f : 1.f;
                float sig = 1.f / (1.f + __expf(-sm * z));
                float a = isg ? fmaf(sig, 2.f, -1.f) : sig;
                const int u = lane & 7;
                float i_ = __shfl_sync(0xffffffffu, a, u);
                float f_ = __shfl_sync(0xffffffffu, a, 8 + u);
                float g_ = __shfl_sync(0xffffffffu, a, 16 + u);
                float o_ = __shfl_sync(0xffffffffu, a, 24 + u);
                if (lane < kUnitsPerCTA) {
                    creg = fmaf(f_, creg, i_ * g_);
                    float tc = 2.f / (1.f + __expf(-2.f * creg)) - 1.f;
                    H0[(size_t)e * kNH + b * kUnitsPerCTA + lane] = o_ * tc;
                }
                __syncwarp();
                if (lane == 0) {
                    int nv = e + 1;
                    asm volatile("st.release.gpu.global.u32 [%0], %1;"
                                 :: "l"(prog0 + b * kFlagStride), "r"(nv) : "memory");
                }
            }
        }
    } else {
        // ================= group B: layer 1 =================
        const int wb = warp - 8;
        const int tb = tid & 255;
        const __half2* wIh = sW1i + (size_t)(wb * 4) * 512;
        const __half2* wHh = sW1h + (size_t)(wb * 4) * 512;
        float creg = 0.f;
        const int* p00 = prog0 + (lane * 4 + 0) * kFlagStride;
        const int* p01 = prog0 + (lane * 4 + 1) * kFlagStride;
        const int* p02 = prog0 + (lane * 4 + 2) * kFlagStride;
        const int* p03 = prog0 + (lane * 4 + 3) * kFlagStride;
        const int* p10 = prog1 + (lane * 4 + 0) * kFlagStride;
        const int* p11 = prog1 + (lane * 4 + 1) * kFlagStride;
        const int* p12 = prog1 + (lane * 4 + 2) * kFlagStride;
        const int* p13 = prog1 + (lane * 4 + 3) * kFlagStride;
        float bias = (lane < 32) ? sBias1[lane] : 0.f;

        for (int e = 0; e < kT; e++) {
            // wait for H0[e] (prog0 >= e+1) and H1[e-1] (prog1 >= e)
            if (warp == 8) {
                const int need0 = e + 1, need1 = e;
                bool ok;
                do {
                    int a0, a1, a2, a3, c0, c1, c2, c3;
                    asm volatile("ld.acquire.gpu.global.u32 %0, [%1];" : "=r"(a0) : "l"(p00) : "memory");
                    asm volatile("ld.acquire.gpu.global.u32 %0, [%1];" : "=r"(a1) : "l"(p01) : "memory");
                    asm volatile("ld.acquire.gpu.global.u32 %0, [%1];" : "=r"(a2) : "l"(p02) : "memory");
                    asm volatile("ld.acquire.gpu.global.u32 %0, [%1];" : "=r"(a3) : "l"(p03) : "memory");
                    asm volatile("ld.acquire.gpu.global.u32 %0, [%1];" : "=r"(c0) : "l"(p10) : "memory");
                    asm volatile("ld.acquire.gpu.global.u32 %0, [%1];" : "=r"(c1) : "l"(p11) : "memory");
                    asm volatile("ld.acquire.gpu.global.u32 %0, [%1];" : "=r"(c2) : "l"(p12) : "memory");
                    asm volatile("ld.acquire.gpu.global.u32 %0, [%1];" : "=r"(c3) : "l"(p13) : "memory");
                    ok = (a0 >= need0) & (a1 >= need0) & (a2 >= need0) & (a3 >= need0) &
                         (c0 >= need1) & (c1 >= need1) & (c2 >= need1) & (c3 >= need1);
                } while (!__all_sync(0xffffffffu, ok));
            }
            asm volatile("bar.sync 2, 256;" ::: "memory");
            ((float4*)sH0b)[tb] = __ldcg((const float4*)(H0 + (size_t)e * kNH) + tb);
            if (e > 0)
                ((float4*)sH1b)[tb] = __ldcg((const float4*)(H1 + (size_t)(e - 1) * kNH) + tb);
            asm volatile("bar.sync 2, 256;" ::: "memory");

            // matvec: z1 rows = W_ih1 @ h0[e] + W_hh1 @ h1[e-1], 4 rows/warp
            const float2* h0p = (const float2*)sH0b;
            const float2* h1p = (const float2*)sH1b;
            float s0 = 0.f, s1 = 0.f, s2 = 0.f, s3 = 0.f;
#pragma unroll
            for (int j = 0; j < 16; j++) {
                const int idx = j * 32 + lane;
                float2 hv = h0p[idx];
                float2 w0 = __half22float2(wIh[idx]);
                float2 w1 = __half22float2(wIh[512 + idx]);
                float2 w2 = __half22float2(wIh[1024 + idx]);
                float2 w3 = __half22float2(wIh[1536 + idx]);
                s0 = fmaf(w0.x, hv.x, fmaf(w0.y, hv.y, s0));
                s1 = fmaf(w1.x, hv.x, fmaf(w1.y, hv.y, s1));
                s2 = fmaf(w2.x, hv.x, fmaf(w2.y, hv.y, s2));
                s3 = fmaf(w3.x, hv.x, fmaf(w3.y, hv.y, s3));
            }
#pragma unroll
            for (int j = 0; j < 16; j++) {
                const int idx = j * 32 + lane;
                float2 hv = h1p[idx];
                float2 w0 = __half22float2(wHh[idx]);
                float2 w1 = __half22float2(wHh[512 + idx]);
                float2 w2 = __half22float2(wHh[1024 + idx]);
                float2 w3 = __half22float2(wHh[1536 + idx]);
                s0 = fmaf(w0.x, hv.x, fmaf(w0.y, hv.y, s0));
                s1 = fmaf(w1.x, hv.x, fmaf(w1.y, hv.y, s1));
                s2 = fmaf(w2.x, hv.x, fmaf(w2.y, hv.y, s2));
                s3 = fmaf(w3.x, hv.x, fmaf(w3.y, hv.y, s3));
            }
#pragma unroll
            for (int off = 16; off; off >>= 1) {
                s0 += __shfl_xor_sync(0xffffffffu, s0, off);
                s1 += __shfl_xor_sync(0xffffffffu, s1, off);
                s2 += __shfl_xor_sync(0xffffffffu, s2, off);
                s3 += __shfl_xor_sync(0xffffffffu, s3, off);
            }
            if (lane == 0) {
                float* d = &sDotB[e & 1][wb * 4];
                d[0] = s0; d[1] = s1; d[2] = s2; d[3] = s3;
            }
            asm volatile("bar.sync 2, 256;" ::: "memory");

            if (warp == 8) {
                float z = sDotB[e & 1][lane] + bias;
                const bool isg = (lane >= 16) & (lane < 24);
                const float sm = isg ? 2.f : 1.f;
                float sig = 1.f / (1.f + __expf(-sm * z));
                float a = isg ? fmaf(sig, 2.f, -1.f) : sig;
                const int u = lane & 7;
                float i_ = __shfl_sync(0xffffffffu, a, u);
                float f_ = __shfl_sync(0xffffffffu, a, 8 + u);
                float g_ = __shfl_sync(0xffffffffu, a, 16 + u);
                float o_ = __shfl_sync(0xffffffffu, a, 24 + u);
                if (lane < kUnitsPerCTA) {
                    creg = fmaf(f_, creg, i_ * g_);
                    float tc = 2.f / (1.f + __expf(-2.f * creg)) - 1.f;
                    H1[(size_t)e * kNH + b * kUnitsPerCTA + lane] = o_ * tc;
                }
                __syncwarp();
                if (lane == 0) {
                    int nv = e + 1;
                    asm volatile("st.release.gpu.global.u32 [%0], %1;"
                                 :: "l"(prog1 + b * kFlagStride), "r"(nv) : "memory");
                }
            }
        }
    }
}

// ---------------- softmax over NO=512 per row ----------------
__global__ __launch_bounds__(256) void softmax_rows(
    const float* __restrict__ L, float* __restrict__ out)
{
    __shared__ float red[256];
    int t = blockIdx.x, tid = threadIdx.x;
    const float* row = L + (size_t)t * kNO;
    float v0 = row[tid], v1 = row[tid + 256];
    float m = fmaxf(v0, v1);
    red[tid] = m; __syncthreads();
    for (int s = 128; s; s >>= 1) {
        if (tid < s) red[tid] = fmaxf(red[tid], red[tid + s]);
        __syncthreads();
    }
    m = red[0]; __syncthreads();
    float e0 = expf(v0 - m), e1 = expf(v1 - m);
    red[tid] = e0 + e1; __syncthreads();
    for (int s = 128; s; s >>= 1) {
        if (tid < s) red[tid] += red[tid + s];
        __syncthreads();
    }
    float inv = 1.f / red[0];
    out[(size_t)t * kNO + tid]       = e0 * inv;
    out[(size_t)t * kNO + tid + 256] = e1 * inv;
}

// ---------------- value head: out[t] = H1[t] . w_val + b_val ----------------
__global__ __launch_bounds__(256) void value_head(
    const float* __restrict__ H1, const float* __restrict__ wv,
    const float* __restrict__ bv, float* __restrict__ out)
{
    __shared__ float red[256];
    int t = blockIdx.x, tid = threadIdx.x;
    const float* h = H1 + (size_t)t * kNH;
    float s = 0.f;
    for (int k = tid; k < kNH; k += 256) s += h[k] * wv[k];
    red[tid] = s; __syncthreads();
    for (int r = 128; r; r >>= 1) {
        if (tid < r) red[tid] += red[tid + r];
        __syncthreads();
    }
    if (tid == 0) out[t] = red[0] + bv[0];
}

// ---------------- launch ----------------
extern "C" void kernel_launch(void* const* d_in, const int* in_sizes, int n_in,
                              void* d_out, int out_size)
{
    (void)in_sizes; (void)n_in; (void)out_size;
    const float* x     = (const float*)d_in[0];
    const float* w_ih0 = (const float*)d_in[1];
    const float* w_hh0 = (const float*)d_in[2];
    const float* b_ih0 = (const float*)d_in[3];
    const float* b_hh0 = (const float*)d_in[4];
    const float* w_ih1 = (const float*)d_in[5];
    const float* w_hh1 = (const float*)d_in[6];
    const float* b_ih1 = (const float*)d_in[7];
    const float* b_hh1 = (const float*)d_in[8];
    const float* w_pol = (const float*)d_in[9];
    const float* b_pol = (const float*)d_in[10];
    const float* w_val = (const float*)d_in[11];
    const float* b_val = (const float*)d_in[12];
    float* out = (float*)d_out;

    float *Z, *H0, *H1;
    int* prog;
    cudaGetSymbolAddress((void**)&Z, g_Z);
    cudaGetSymbolAddress((void**)&H0, g_H0);
    cudaGetSymbolAddress((void**)&H1, g_H1);
    cudaGetSymbolAddress((void**)&prog, g_prog);

    const int smem = 3 * 32 * 512 * (int)sizeof(__half2);  // 192 KB dynamic (weights)
    cudaFuncSetAttribute(lstm_fused, cudaFuncAttributeMaxDynamicSharedMemorySize, smem);

    // reset progress flags every launch (replay-deterministic)
    zero_prog_kernel<<<(2 * kNumCTA * kFlagStride + 255) / 256, 256>>>(
        prog, 2 * kNumCTA * kFlagStride);

    // Z0 = X @ w_ih0^T + (b_ih0 + b_hh0)
    gemm_nt<<<dim3(kNG / 128, kT / 128), 256>>>(x, w_ih0, b_ih0, b_hh0, Z, kT, kNG, kNS);
    // fused 2-layer recurrence -> H0, H1 (layer-1 x-projection computed in-kernel)
    lstm_fused<<<kNumCTA, 512, smem>>>(Z, w_hh0, w_ih1, w_hh1, b_ih1, b_hh1,
                                       H0, H1, prog, prog + kNumCTA * kFlagStride);
    // policy logits = H1 @ w_pol^T + b_pol (into Z scratch)
    gemm_nt<<<dim3(kNO / 128, kT / 128), 256>>>(H1, w_pol, b_pol, nullptr, Z, kT, kNO, kNH);
    // softmax -> out[0 : T*NO)
    softmax_rows<<<kT, 256>>>(Z, out);
    // value -> out[T*NO : T*NO + T)
    value_head<<<kT, 256>>>(H1, w_val, b_val, out + (size_t)kT * kNO);
}

// round 11
// speedup vs baseline: 6.9506x; 1.4154x over previous
#include <cuda_runtime.h>
#include <cuda_fp16.h>
#include <cstdint>

// Problem dims
constexpr int kT  = 8192;
constexpr int kNS = 512;
constexpr int kNH = 1024;
constexpr int kNO = 512;
constexpr int kNG = 4 * kNH;  // 4096 gate rows

constexpr int kNumCTA = 128;                 // persistent CTAs (<148 SMs -> co-resident)
constexpr int kUnitsPerCTA = kNH / kNumCTA;  // 8 hidden units per CTA
// packed flags: 4 CTA flags per 16B line, lines 256 B apart -> 32 groups, one
// ld.acquire.v4 per lane covers all 128 CTAs.
constexpr int kGrpStride = 64;               // ints between groups (256 B)

// ---------------- scratch (static device allocations; no cudaMalloc) ----------------
__device__ float g_Z[(size_t)kT * kNG];    // 128 MB: layer-0 gate preactivations / logits
__device__ float g_H0[(size_t)kT * kNH];   // 32 MB
__device__ float g_H1[(size_t)kT * kNH];   // 32 MB
__device__ __align__(256) int g_prog[2 * 32 * kGrpStride];  // prog0 | prog1 packed flags

// ---------------- init ----------------
__global__ void zero_prog_kernel(int* p, int n) {
    int i = blockIdx.x * blockDim.x + threadIdx.x;
    if (i < n) p[i] = 0;
}

// ---------------- fp32 tiled GEMM: C[M,N] = A[M,K] * B[N,K]^T (+bias1[n]+bias2[n]) ----
__global__ __launch_bounds__(256) void gemm_nt(
    const float* __restrict__ A, const float* __restrict__ B,
    const float* __restrict__ b1, const float* __restrict__ b2,
    float* __restrict__ C, int M, int N, int K)
{
    __shared__ float As[8][128];
    __shared__ float Bs[8][128];
    const int tid = threadIdx.x;
    const int m0 = blockIdx.y * 128;
    const int n0 = blockIdx.x * 128;
    const int ty = tid >> 4;
    const int tx = tid & 15;
    const int lrow = tid >> 1;
    const int lk = (tid & 1) * 4;
    const float* Ap = A + (size_t)(m0 + lrow) * K + lk;
    const float* Bp = B + (size_t)(n0 + lrow) * K + lk;

    float acc[8][8];
#pragma unroll
    for (int i = 0; i < 8; i++)
#pragma unroll
        for (int j = 0; j < 8; j++) acc[i][j] = 0.f;

    for (int k0 = 0; k0 < K; k0 += 8) {
        float4 av = *(const float4*)(Ap + k0);
        float4 bv = *(const float4*)(Bp + k0);
        As[lk + 0][lrow] = av.x; As[lk + 1][lrow] = av.y;
        As[lk + 2][lrow] = av.z; As[lk + 3][lrow] = av.w;
        Bs[lk + 0][lrow] = bv.x; Bs[lk + 1][lrow] = bv.y;
        Bs[lk + 2][lrow] = bv.z; Bs[lk + 3][lrow] = bv.w;
        __syncthreads();
#pragma unroll
        for (int kk = 0; kk < 8; kk++) {
            float a[8], b[8];
#pragma unroll
            for (int i = 0; i < 8; i++) a[i] = As[kk][i * 16 + ty];
#pragma unroll
            for (int j = 0; j < 8; j++) b[j] = Bs[kk][j * 16 + tx];
#pragma unroll
            for (int i = 0; i < 8; i++)
#pragma unroll
                for (int j = 0; j < 8; j++) acc[i][j] += a[i] * b[j];
        }
        __syncthreads();
    }

#pragma unroll
    for (int j = 0; j < 8; j++) {
        int n = n0 + j * 16 + tx;
        float bias = 0.f;
        if (b1) bias += b1[n];
        if (b2) bias += b2[n];
#pragma unroll
        for (int i = 0; i < 8; i++) {
            int m = m0 + i * 16 + ty;
            C[(size_t)m * N + n] = acc[i][j] + bias;
        }
    }
}

// ---------------- fused 2-layer persistent LSTM recurrence -------------------------
// group A (warps 8-15, critical warp 15): layer 0
// group B (warps 0-7,  special  warp 7):  layer 1, lags A by one epoch
// Flags packed 4-per-16B-line: poller reads all 128 with one v4/lane.
// B's layer-0 dependency is satisfied via an SMEM mailbox written by A's poller
// (A proving prog0 >= e+1 implies H0[e] globally visible) -> B produces no
// L2 poll traffic for prog0.
__global__ __launch_bounds__(512) void lstm_fused(
    const float* __restrict__ Z0, const float* __restrict__ Whh0,
    const float* __restrict__ Wih1, const float* __restrict__ Whh1,
    const float* __restrict__ b_ih1, const float* __restrict__ b_hh1,
    float* H0, float* H1, int* prog0, int* prog1)
{
    extern __shared__ __half2 sWdyn[];           // 3 x [32][512] half2 = 192 KB
    __half2* sW0  = sWdyn;                       // W_hh0 (group A)
    __half2* sW1i = sWdyn + 32 * 512;            // W_ih1 (group B)
    __half2* sW1h = sWdyn + 2 * 32 * 512;        // W_hh1 (group B)
    __shared__ float sH0a[kNH];
    __shared__ float sH0b[kNH];
    __shared__ float sH1b[kNH];
    __shared__ float sDotA[2][32];
    __shared__ float sDotB[2][32];
    __shared__ float sBias1[32];
    __shared__ int   sSeen;                      // mailbox: max e with H0[e-1] proven

    const int tid  = threadIdx.x;
    const int b    = blockIdx.x;
    const int warp = tid >> 5;
    const int lane = tid & 31;
    const uint32_t seenAddr = (uint32_t)__cvta_generic_to_shared(&sSeen);

    // ---- load + convert weights (gate-major lr = g*8+u), all 512 threads ----
    for (int i = tid; i < 32 * 512; i += 512) {
        int lr = i >> 9, p = i & 511;
        int g = lr >> 3, u = lr & 7;
        size_t row = (size_t)(g * kNH + b * kUnitsPerCTA + u) * kNH + 2 * p;
        float2 w0 = *(const float2*)(Whh0 + row);
        float2 w1 = *(const float2*)(Wih1 + row);
        float2 w2 = *(const float2*)(Whh1 + row);
        sW0[i]  = __floats2half2_rn(w0.x, w0.y);
        sW1i[i] = __floats2half2_rn(w1.x, w1.y);
        sW1h[i] = __floats2half2_rn(w2.x, w2.y);
    }
    if (tid < 32) {
        int g = tid >> 3, u = tid & 7;
        int idx = g * kNH + b * kUnitsPerCTA + u;
        sBias1[tid] = b_ih1[idx] + b_hh1[idx];
    }
    if (tid < 256) {
        ((float4*)sH0a)[tid] = make_float4(0.f, 0.f, 0.f, 0.f);
        ((float4*)sH1b)[tid] = make_float4(0.f, 0.f, 0.f, 0.f);
    }
    if (tid == 0) sSeen = 0;
    __syncthreads();   // last whole-CTA barrier

    if (warp >= 8) {
        // ================= group A: layer 0 (warps 8-15) =================
        const int wa = warp - 8;
        const int ta = tid - 256;                      // 0..255 within group
        const __half2* wbase = sW0 + (size_t)(wa * 4) * 512;
        float creg = 0.f;
        const int* pf = prog0 + lane * kGrpStride;     // lane's packed flag group
        int* relA = prog0 + (b >> 2) * kGrpStride + (b & 3);

        for (int e = 0; e < kT; e++) {
            float zv = 0.f;
            if (warp == 15)
                zv = Z0[(size_t)e * kNG + (lane >> 3) * kNH + b * kUnitsPerCTA + (lane & 7)];

            if (e > 0) {
                if (warp == 15) {
                    bool ok;
                    do {
                        int4 v;
                        asm volatile("ld.acquire.gpu.global.v4.u32 {%0,%1,%2,%3}, [%4];"
                                     : "=r"(v.x), "=r"(v.y), "=r"(v.z), "=r"(v.w)
                                     : "l"(pf) : "memory");
                        ok = (v.x >= e) & (v.y >= e) & (v.z >= e) & (v.w >= e);
                    } while (!__all_sync(0xffffffffu, ok));
                    if (lane == 0)
                        asm volatile("st.release.cta.shared.u32 [%0], %1;"
                                     :: "r"(seenAddr), "r"(e) : "memory");
                }
                asm volatile("bar.sync 1, 256;" ::: "memory");
                ((float4*)sH0a)[ta] = __ldcg((const float4*)(H0 + (size_t)(e - 1) * kNH) + ta);
                asm volatile("bar.sync 1, 256;" ::: "memory");
            }

            // matvec: 4 rows/warp over sH0a
            const float2* sHp = (const float2*)sH0a;
            float s0 = 0.f, s1 = 0.f, s2 = 0.f, s3 = 0.f;
#pragma unroll
            for (int j = 0; j < 16; j++) {
                const int idx = j * 32 + lane;
                float2 hv = sHp[idx];
                float2 w0 = __half22float2(wbase[idx]);
                float2 w1 = __half22float2(wbase[512 + idx]);
                float2 w2 = __half22float2(wbase[1024 + idx]);
                float2 w3 = __half22float2(wbase[1536 + idx]);
                s0 = fmaf(w0.x, hv.x, fmaf(w0.y, hv.y, s0));
                s1 = fmaf(w1.x, hv.x, fmaf(w1.y, hv.y, s1));
                s2 = fmaf(w2.x, hv.x, fmaf(w2.y, hv.y, s2));
                s3 = fmaf(w3.x, hv.x, fmaf(w3.y, hv.y, s3));
            }
#pragma unroll
            for (int off = 16; off; off >>= 1) {
                s0 += __shfl_xor_sync(0xffffffffu, s0, off);
                s1 += __shfl_xor_sync(0xffffffffu, s1, off);
                s2 += __shfl_xor_sync(0xffffffffu, s2, off);
                s3 += __shfl_xor_sync(0xffffffffu, s3, off);
            }
            if (lane == 0) {
                float* d = &sDotA[e & 1][wa * 4];
                d[0] = s0; d[1] = s1; d[2] = s2; d[3] = s3;
            }
            asm volatile("bar.sync 1, 256;" ::: "memory");

            if (warp == 15) {
                float z = sDotA[e & 1][lane] + zv;
                const bool isg = (lane >= 16) & (lane < 24);
                const float sm = isg ? 2.f : 1.f;
                float sig = 1.f / (1.f + __expf(-sm * z));
                float a = isg ? fmaf(sig, 2.f, -1.f) : sig;
                const int u = lane & 7;
                float i_ = __shfl_sync(0xffffffffu, a, u);
                float f_ = __shfl_sync(0xffffffffu, a, 8 + u);
                float g_ = __shfl_sync(0xffffffffu, a, 16 + u);
                float o_ = __shfl_sync(0xffffffffu, a, 24 + u);
                if (lane < kUnitsPerCTA) {
                    creg = fmaf(f_, creg, i_ * g_);
                    float tc = 2.f / (1.f + __expf(-2.f * creg)) - 1.f;
                    H0[(size_t)e * kNH + b * kUnitsPerCTA + lane] = o_ * tc;
                }
                __syncwarp();
                if (lane == 0) {
                    int nv = e + 1;
                    asm volatile("st.release.gpu.global.u32 [%0], %1;"
                                 :: "l"(relA), "r"(nv) : "memory");
                }
            }
        }
        // post-loop: prove prog0 >= kT so B's last epoch can proceed
        if (warp == 15) {
            bool ok;
            do {
                int4 v;
                asm volatile("ld.acquire.gpu.global.v4.u32 {%0,%1,%2,%3}, [%4];"
                             : "=r"(v.x), "=r"(v.y), "=r"(v.z), "=r"(v.w)
                             : "l"(pf) : "memory");
                ok = (v.x >= kT) & (v.y >= kT) & (v.z >= kT) & (v.w >= kT);
            } while (!__all_sync(0xffffffffu, ok));
            if (lane == 0)
                asm volatile("st.release.cta.shared.u32 [%0], %1;"
                             :: "r"(seenAddr), "r"(kT) : "memory");
        }
    } else {
        // ================= group B: layer 1 (warps 0-7) =================
        const int wb = warp;
        const int tb = tid;                            // 0..255 within group
        const __half2* wIh = sW1i + (size_t)(wb * 4) * 512;
        const __half2* wHh = sW1h + (size_t)(wb * 4) * 512;
        float creg = 0.f;
        const int* pf1 = prog1 + lane * kGrpStride;
        int* relB = prog1 + (b >> 2) * kGrpStride + (b & 3);
        const float bias = sBias1[lane];

        for (int e = 0; e < kT; e++) {
            if (warp == 7) {
                // layer-0 dep: SMEM mailbox (sSeen >= e+1  <=>  prog0 >= e+1 proven)
                int sv;
                do {
                    asm volatile("ld.acquire.cta.shared.u32 %0, [%1];"
                                 : "=r"(sv) : "r"(seenAddr) : "memory");
                } while (sv < e + 1);
                // layer-1 dep: prog1 >= e
                if (e > 0) {
                    bool ok;
                    do {
                        int4 v;
                        asm volatile("ld.acquire.gpu.global.v4.u32 {%0,%1,%2,%3}, [%4];"
                                     : "=r"(v.x), "=r"(v.y), "=r"(v.z), "=r"(v.w)
                                     : "l"(pf1) : "memory");
                        ok = (v.x >= e) & (v.y >= e) & (v.z >= e) & (v.w >= e);
                    } while (!__all_sync(0xffffffffu, ok));
                }
            }
            asm volatile("bar.sync 2, 256;" ::: "memory");
            ((float4*)sH0b)[tb] = __ldcg((const float4*)(H0 + (size_t)e * kNH) + tb);
            if (e > 0)
                ((float4*)sH1b)[tb] = __ldcg((const float4*)(H1 + (size_t)(e - 1) * kNH) + tb);
            asm volatile("bar.sync 2, 256;" ::: "memory");

            // z1 = W_ih1 @ h0[e] + W_hh1 @ h1[e-1], 4 rows/warp
            const float2* h0p = (const float2*)sH0b;
            const float2* h1p = (const float2*)sH1b;
            float s0 = 0.f, s1 = 0.f, s2 = 0.f, s3 = 0.f;
#pragma unroll
            for (int j = 0; j < 16; j++) {
                const int idx = j * 32 + lane;
                float2 hv = h0p[idx];
                float2 w0 = __half22float2(wIh[idx]);
                float2 w1 = __half22float2(wIh[512 + idx]);
                float2 w2 = __half22float2(wIh[1024 + idx]);
                float2 w3 = __half22float2(wIh[1536 + idx]);
                s0 = fmaf(w0.x, hv.x, fmaf(w0.y, hv.y, s0));
                s1 = fmaf(w1.x, hv.x, fmaf(w1.y, hv.y, s1));
                s2 = fmaf(w2.x, hv.x, fmaf(w2.y, hv.y, s2));
                s3 = fmaf(w3.x, hv.x, fmaf(w3.y, hv.y, s3));
            }
#pragma unroll
            for (int j = 0; j < 16; j++) {
                const int idx = j * 32 + lane;
                float2 hv = h1p[idx];
                float2 w0 = __half22float2(wHh[idx]);
                float2 w1 = __half22float2(wHh[512 + idx]);
                float2 w2 = __half22float2(wHh[1024 + idx]);
                float2 w3 = __half22float2(wHh[1536 + idx]);
                s0 = fmaf(w0.x, hv.x, fmaf(w0.y, hv.y, s0));
                s1 = fmaf(w1.x, hv.x, fmaf(w1.y, hv.y, s1));
                s2 = fmaf(w2.x, hv.x, fmaf(w2.y, hv.y, s2));
                s3 = fmaf(w3.x, hv.x, fmaf(w3.y, hv.y, s3));
            }
#pragma unroll
            for (int off = 16; off; off >>= 1) {
                s0 += __shfl_xor_sync(0xffffffffu, s0, off);
                s1 += __shfl_xor_sync(0xffffffffu, s1, off);
                s2 += __shfl_xor_sync(0xffffffffu, s2, off);
                s3 += __shfl_xor_sync(0xffffffffu, s3, off);
            }
            if (lane == 0) {
                float* d = &sDotB[e & 1][wb * 4];
                d[0] = s0; d[1] = s1; d[2] = s2; d[3] = s3;
            }
            asm volatile("bar.sync 2, 256;" ::: "memory");

            if (warp == 7) {
                float z = sDotB[e & 1][lane] + bias;
                const bool isg = (lane >= 16) & (lane < 24);
                const float sm = isg ? 2.f : 1.f;
                float sig = 1.f / (1.f + __expf(-sm * z));
                float a = isg ? fmaf(sig, 2.f, -1.f) : sig;
                const int u = lane & 7;
                float i_ = __shfl_sync(0xffffffffu, a, u);
                float f_ = __shfl_sync(0xffffffffu, a, 8 + u);
                float g_ = __shfl_sync(0xffffffffu, a, 16 + u);
                float o_ = __shfl_sync(0xffffffffu, a, 24 + u);
                if (lane < kUnitsPerCTA) {
                    creg = fmaf(f_, creg, i_ * g_);
                    float tc = 2.f / (1.f + __expf(-2.f * creg)) - 1.f;
                    H1[(size_t)e * kNH + b * kUnitsPerCTA + lane] = o_ * tc;
                }
                __syncwarp();
                if (lane == 0) {
                    int nv = e + 1;
                    asm volatile("st.release.gpu.global.u32 [%0], %1;"
                                 :: "l"(relB), "r"(nv) : "memory");
                }
            }
        }
    }
}

// ---------------- softmax over NO=512 per row ----------------
__global__ __launch_bounds__(256) void softmax_rows(
    const float* __restrict__ L, float* __restrict__ out)
{
    __shared__ float red[256];
    int t = blockIdx.x, tid = threadIdx.x;
    const float* row = L + (size_t)t * kNO;
    float v0 = row[tid], v1 = row[tid + 256];
    float m = fmaxf(v0, v1);
    red[tid] = m; __syncthreads();
    for (int s = 128; s; s >>= 1) {
        if (tid < s) red[tid] = fmaxf(red[tid], red[tid + s]);
        __syncthreads();
    }
    m = red[0]; __syncthreads();
    float e0 = expf(v0 - m), e1 = expf(v1 - m);
    red[tid] = e0 + e1; __syncthreads();
    for (int s = 128; s; s >>= 1) {
        if (tid < s) red[tid] += red[tid + s];
        __syncthreads();
    }
    float inv = 1.f / red[0];
    out[(size_t)t * kNO + tid]       = e0 * inv;
    out[(size_t)t * kNO + tid + 256] = e1 * inv;
}

// ---------------- value head: out[t] = H1[t] . w_val + b_val ----------------
__global__ __launch_bounds__(256) void value_head(
    const float* __restrict__ H1, const float* __restrict__ wv,
    const float* __restrict__ bv, float* __restrict__ out)
{
    __shared__ float red[256];
    int t = blockIdx.x, tid = threadIdx.x;
    const float* h = H1 + (size_t)t * kNH;
    float s = 0.f;
    for (int k = tid; k < kNH; k += 256) s += h[k] * wv[k];
    red[tid] = s; __syncthreads();
    for (int r = 128; r; r >>= 1) {
        if (tid < r) red[tid] += red[tid + r];
        __syncthreads();
    }
    if (tid == 0) out[t] = red[0] + bv[0];
}

// ---------------- launch ----------------
extern "C" void kernel_launch(void* const* d_in, const int* in_sizes, int n_in,
                              void* d_out, int out_size)
{
    (void)in_sizes; (void)n_in; (void)out_size;
    const float* x     = (const float*)d_in[0];
    const float* w_ih0 = (const float*)d_in[1];
    const float* w_hh0 = (const float*)d_in[2];
    const float* b_ih0 = (const float*)d_in[3];
    const float* b_hh0 = (const float*)d_in[4];
    const float* w_ih1 = (const float*)d_in[5];
    const float* w_hh1 = (const float*)d_in[6];
    const float* b_ih1 = (const float*)d_in[7];
    const float* b_hh1 = (const float*)d_in[8];
    const float* w_pol = (const float*)d_in[9];
    const float* b_pol = (const float*)d_in[10];
    const float* w_val = (const float*)d_in[11];
    const float* b_val = (const float*)d_in[12];
    float* out = (float*)d_out;

    float *Z, *H0, *H1;
    int* prog;
    cudaGetSymbolAddress((void**)&Z, g_Z);
    cudaGetSymbolAddress((void**)&H0, g_H0);
    cudaGetSymbolAddress((void**)&H1, g_H1);
    cudaGetSymbolAddress((void**)&prog, g_prog);

    const int smem = 3 * 32 * 512 * (int)sizeof(__half2);  // 192 KB dynamic (weights)
    cudaFuncSetAttribute(lstm_fused, cudaFuncAttributeMaxDynamicSharedMemorySize, smem);

    // reset packed progress flags every launch (replay-deterministic)
    zero_prog_kernel<<<(2 * 32 * kGrpStride + 255) / 256, 256>>>(prog, 2 * 32 * kGrpStride);

    // Z0 = X @ w_ih0^T + (b_ih0 + b_hh0)
    gemm_nt<<<dim3(kNG / 128, kT / 128), 256>>>(x, w_ih0, b_ih0, b_hh0, Z, kT, kNG, kNS);
    // fused 2-layer recurrence -> H0, H1
    lstm_fused<<<kNumCTA, 512, smem>>>(Z, w_hh0, w_ih1, w_hh1, b_ih1, b_hh1,
                                       H0, H1, prog, prog + 32 * kGrpStride);
    // policy logits = H1 @ w_pol^T + b_pol (into Z scratch)
    gemm_nt<<<dim3(kNO / 128, kT / 128), 256>>>(H1, w_pol, b_pol, nullptr, Z, kT, kNO, kNH);
    // softmax -> out[0 : T*NO)
    softmax_rows<<<kT, 256>>>(Z, out);
    // value -> out[T*NO : T*NO + T)
    value_head<<<kT, 256>>>(H1, w_val, b_val, out + (size_t)kT * kNO);
}

// round 12
// speedup vs baseline: 8.4945x; 1.2221x over previous
#include <cuda_runtime.h>
#include <cuda_fp16.h>
#include <cstdint>

// Problem dims
constexpr int kT  = 8192;
constexpr int kNS = 512;
constexpr int kNH = 1024;
constexpr int kNO = 512;
constexpr int kNG = 4 * kNH;  // 4096 gate rows

constexpr int kNumCTA = 128;                 // persistent CTAs (<148 SMs -> co-resident)
constexpr int kUnitsPerCTA = kNH / kNumCTA;  // 8 hidden units per CTA

// ---------------- scratch (static device allocations; no cudaMalloc) ----------------
__device__ float g_Z[(size_t)kT * kNG];    // 128 MB: layer-0 gate preactivations / logits
__device__ float g_H0[(size_t)kT * kNH];   // 32 MB (NaN-canary protocol)
__device__ float g_H1[(size_t)kT * kNH];   // 32 MB (NaN-canary protocol)

// ---------------- NaN prefill: data-as-signal canary ----------------
__global__ void prefill_nan(float4* a, int n4) {
    int i = blockIdx.x * blockDim.x + threadIdx.x;
    const float qn = __int_as_float(0x7FC00000);
    float4 v = make_float4(qn, qn, qn, qn);
    if (i < n4) a[i] = v;
}

// ---------------- fp32 tiled GEMM: C[M,N] = A[M,K] * B[N,K]^T (+bias1[n]+bias2[n]) ----
__global__ __launch_bounds__(256) void gemm_nt(
    const float* __restrict__ A, const float* __restrict__ B,
    const float* __restrict__ b1, const float* __restrict__ b2,
    float* __restrict__ C, int M, int N, int K)
{
    __shared__ float As[8][128];
    __shared__ float Bs[8][128];
    const int tid = threadIdx.x;
    const int m0 = blockIdx.y * 128;
    const int n0 = blockIdx.x * 128;
    const int ty = tid >> 4;
    const int tx = tid & 15;
    const int lrow = tid >> 1;
    const int lk = (tid & 1) * 4;
    const float* Ap = A + (size_t)(m0 + lrow) * K + lk;
    const float* Bp = B + (size_t)(n0 + lrow) * K + lk;

    float acc[8][8];
#pragma unroll
    for (int i = 0; i < 8; i++)
#pragma unroll
        for (int j = 0; j < 8; j++) acc[i][j] = 0.f;

    for (int k0 = 0; k0 < K; k0 += 8) {
        float4 av = *(const float4*)(Ap + k0);
        float4 bv = *(const float4*)(Bp + k0);
        As[lk + 0][lrow] = av.x; As[lk + 1][lrow] = av.y;
        As[lk + 2][lrow] = av.z; As[lk + 3][lrow] = av.w;
        Bs[lk + 0][lrow] = bv.x; Bs[lk + 1][lrow] = bv.y;
        Bs[lk + 2][lrow] = bv.z; Bs[lk + 3][lrow] = bv.w;
        __syncthreads();
#pragma unroll
        for (int kk = 0; kk < 8; kk++) {
            float a[8], b[8];
#pragma unroll
            for (int i = 0; i < 8; i++) a[i] = As[kk][i * 16 + ty];
#pragma unroll
            for (int j = 0; j < 8; j++) b[j] = Bs[kk][j * 16 + tx];
#pragma unroll
            for (int i = 0; i < 8; i++)
#pragma unroll
                for (int j = 0; j < 8; j++) acc[i][j] += a[i] * b[j];
        }
        __syncthreads();
    }

#pragma unroll
    for (int j = 0; j < 8; j++) {
        int n = n0 + j * 16 + tx;
        float bias = 0.f;
        if (b1) bias += b1[n];
        if (b2) bias += b2[n];
#pragma unroll
        for (int i = 0; i < 8; i++) {
            int m = m0 + i * 16 + ty;
            C[(size_t)m * N + n] = acc[i][j] + bias;
        }
    }
}

// ---- helpers: volatile data-as-signal loads/stores ----
__device__ __forceinline__ float4 ld_vol4(const float4* p) {
    float4 v;
    asm volatile("ld.volatile.global.v4.f32 {%0,%1,%2,%3}, [%4];"
                 : "=f"(v.x), "=f"(v.y), "=f"(v.z), "=f"(v.w) : "l"(p) : "memory");
    return v;
}
__device__ __forceinline__ void st_vol(float* p, float v) {
    asm volatile("st.volatile.global.f32 [%0], %1;" :: "l"(p), "f"(v) : "memory");
}
__device__ __forceinline__ bool ok4(float4 v) {
    return (v.x == v.x) & (v.y == v.y) & (v.z == v.z) & (v.w == v.w);
}

// ---------------- fused 2-layer persistent LSTM recurrence -------------------------
// group A (warps 8-15, critical warp 15): layer 0
// group B (warps 0-7,  special  warp 7):  layer 1, lags A by one epoch
// NaN-canary protocol: H rows are pre-filled with NaN; publishers write h via
// volatile 4B stores; pollers read the DATA itself (ld.volatile.v4) and treat
// all-finite as ready -> discovery and staging are fused (poller STSes its
// registers into SMEM). No flag arrays, no tag release, no separate stage read.
__global__ __launch_bounds__(512) void lstm_fused(
    const float* __restrict__ Z0, const float* __restrict__ Whh0,
    const float* __restrict__ Wih1, const float* __restrict__ Whh1,
    const float* __restrict__ b_ih1, const float* __restrict__ b_hh1,
    float* H0, float* H1)
{
    extern __shared__ __half2 sWdyn[];           // 3 x [32][512] half2 = 192 KB
    __half2* sW0  = sWdyn;                       // W_hh0 (group A)
    __half2* sW1i = sWdyn + 32 * 512;            // W_ih1 (group B)
    __half2* sW1h = sWdyn + 2 * 32 * 512;        // W_hh1 (group B)
    __shared__ float sH0a[kNH];
    __shared__ float sH0b[kNH];
    __shared__ float sH1b[kNH];
    __shared__ float sDotA[2][32];
    __shared__ float sDotB[2][32];
    __shared__ float sBias1[32];
    __shared__ int   sSeen;                      // mailbox: sSeen = e  <=>  h0[e-1] proven

    const int tid  = threadIdx.x;
    const int b    = blockIdx.x;
    const int warp = tid >> 5;
    const int lane = tid & 31;
    const uint32_t seenAddr = (uint32_t)__cvta_generic_to_shared(&sSeen);

    // ---- load + convert weights (gate-major lr = g*8+u), all 512 threads ----
    for (int i = tid; i < 32 * 512; i += 512) {
        int lr = i >> 9, p = i & 511;
        int g = lr >> 3, u = lr & 7;
        size_t row = (size_t)(g * kNH + b * kUnitsPerCTA + u) * kNH + 2 * p;
        float2 w0 = *(const float2*)(Whh0 + row);
        float2 w1 = *(const float2*)(Wih1 + row);
        float2 w2 = *(const float2*)(Whh1 + row);
        sW0[i]  = __floats2half2_rn(w0.x, w0.y);
        sW1i[i] = __floats2half2_rn(w1.x, w1.y);
        sW1h[i] = __floats2half2_rn(w2.x, w2.y);
    }
    if (tid < 32) {
        int g = tid >> 3, u = tid & 7;
        int idx = g * kNH + b * kUnitsPerCTA + u;
        sBias1[tid] = b_ih1[idx] + b_hh1[idx];
    }
    if (tid < 256) {
        ((float4*)sH0a)[tid] = make_float4(0.f, 0.f, 0.f, 0.f);
        ((float4*)sH1b)[tid] = make_float4(0.f, 0.f, 0.f, 0.f);
    }
    if (tid == 0) sSeen = 0;
    __syncthreads();   // last whole-CTA barrier

    if (warp >= 8) {
        // ================= group A: layer 0 (warps 8-15) =================
        const int wa = warp - 8;
        const __half2* wbase = sW0 + (size_t)(wa * 4) * 512;
        float creg = 0.f;

        for (int e = 0; e < kT; e++) {
            float zv = 0.f;
            if (warp == 15)
                zv = Z0[(size_t)e * kNG + (lane >> 3) * kNH + b * kUnitsPerCTA + (lane & 7)];

            if (e > 0) {
                if (warp == 15) {
                    // fused discovery+stage: poll the h0[e-1] DATA itself
                    const float4* row = (const float4*)(H0 + (size_t)(e - 1) * kNH);
                    float4 r0, r1, r2, r3, r4, r5, r6, r7;
                    bool ok;
                    do {
                        r0 = ld_vol4(row + 0 * 32 + lane);
                        r1 = ld_vol4(row + 1 * 32 + lane);
                        r2 = ld_vol4(row + 2 * 32 + lane);
                        r3 = ld_vol4(row + 3 * 32 + lane);
                        r4 = ld_vol4(row + 4 * 32 + lane);
                        r5 = ld_vol4(row + 5 * 32 + lane);
                        r6 = ld_vol4(row + 6 * 32 + lane);
                        r7 = ld_vol4(row + 7 * 32 + lane);
                        ok = ok4(r0) & ok4(r1) & ok4(r2) & ok4(r3)
                           & ok4(r4) & ok4(r5) & ok4(r6) & ok4(r7);
                    } while (!__all_sync(0xffffffffu, ok));
                    float4* d = (float4*)sH0a;
                    d[0 * 32 + lane] = r0; d[1 * 32 + lane] = r1;
                    d[2 * 32 + lane] = r2; d[3 * 32 + lane] = r3;
                    d[4 * 32 + lane] = r4; d[5 * 32 + lane] = r5;
                    d[6 * 32 + lane] = r6; d[7 * 32 + lane] = r7;
                    if (lane == 0)
                        asm volatile("st.release.cta.shared.u32 [%0], %1;"
                                     :: "r"(seenAddr), "r"(e) : "memory");
                }
                asm volatile("bar.sync 1, 256;" ::: "memory");   // sH0a ready
            }

            // matvec: 4 rows/warp over sH0a
            const float2* sHp = (const float2*)sH0a;
            float2 h2[16];
#pragma unroll
            for (int j = 0; j < 16; j++) h2[j] = sHp[j * 32 + lane];
            float s0 = 0.f, s1 = 0.f, s2 = 0.f, s3 = 0.f;
#pragma unroll
            for (int j = 0; j < 16; j++) {
                const int idx = j * 32 + lane;
                float2 w0 = __half22float2(wbase[idx]);
                float2 w1 = __half22float2(wbase[512 + idx]);
                float2 w2 = __half22float2(wbase[1024 + idx]);
                float2 w3 = __half22float2(wbase[1536 + idx]);
                s0 = fmaf(w0.x, h2[j].x, fmaf(w0.y, h2[j].y, s0));
                s1 = fmaf(w1.x, h2[j].x, fmaf(w1.y, h2[j].y, s1));
                s2 = fmaf(w2.x, h2[j].x, fmaf(w2.y, h2[j].y, s2));
                s3 = fmaf(w3.x, h2[j].x, fmaf(w3.y, h2[j].y, s3));
            }
#pragma unroll
            for (int off = 16; off; off >>= 1) {
                s0 += __shfl_xor_sync(0xffffffffu, s0, off);
                s1 += __shfl_xor_sync(0xffffffffu, s1, off);
                s2 += __shfl_xor_sync(0xffffffffu, s2, off);
                s3 += __shfl_xor_sync(0xffffffffu, s3, off);
            }
            if (lane == 0) {
                float* d = &sDotA[e & 1][wa * 4];
                d[0] = s0; d[1] = s1; d[2] = s2; d[3] = s3;
            }
            asm volatile("bar.sync 1, 256;" ::: "memory");

            if (warp == 15) {
                float z = sDotA[e & 1][lane] + zv;
                const bool isg = (lane >= 16) & (lane < 24);
                const float sm = isg ? 2.f : 1.f;
                float sig = 1.f / (1.f + __expf(-sm * z));
                float a = isg ? fmaf(sig, 2.f, -1.f) : sig;
                const int u = lane & 7;
                float i_ = __shfl_sync(0xffffffffu, a, u);
                float f_ = __shfl_sync(0xffffffffu, a, 8 + u);
                float g_ = __shfl_sync(0xffffffffu, a, 16 + u);
                float o_ = __shfl_sync(0xffffffffu, a, 24 + u);
                if (lane < kUnitsPerCTA) {
                    creg = fmaf(f_, creg, i_ * g_);
                    float tc = 2.f / (1.f + __expf(-2.f * creg)) - 1.f;
                    // publish: data IS the signal (volatile 4B store, never NaN)
                    st_vol(H0 + (size_t)e * kNH + b * kUnitsPerCTA + lane, o_ * tc);
                }
            }
        }
        // post-loop: prove h0[kT-1] complete so B's last epoch can proceed
        if (warp == 15) {
            const float4* row = (const float4*)(H0 + (size_t)(kT - 1) * kNH);
            bool ok;
            do {
                ok = true;
#pragma unroll
                for (int i = 0; i < 8; i++) ok &= ok4(ld_vol4(row + i * 32 + lane));
            } while (!__all_sync(0xffffffffu, ok));
            if (lane == 0)
                asm volatile("st.release.cta.shared.u32 [%0], %1;"
                             :: "r"(seenAddr), "r"(kT) : "memory");
        }
    } else {
        // ================= group B: layer 1 (warps 0-7) =================
        const int wb = warp;
        const int tb = tid;                            // 0..255 within group
        const __half2* wIh = sW1i + (size_t)(wb * 4) * 512;
        const __half2* wHh = sW1h + (size_t)(wb * 4) * 512;
        float creg = 0.f;
        const float bias = sBias1[lane];

        for (int e = 0; e < kT; e++) {
            if (warp == 7) {
                // layer-0 dep: mailbox (sSeen >= e+1  <=>  h0[e] proven visible)
                int sv;
                do {
                    asm volatile("ld.acquire.cta.shared.u32 %0, [%1];"
                                 : "=r"(sv) : "r"(seenAddr) : "memory");
                } while (sv < e + 1);
                // layer-1 dep: NaN-poll h1[e-1] data, fused with staging
                if (e > 0) {
                    const float4* row = (const float4*)(H1 + (size_t)(e - 1) * kNH);
                    float4 r0, r1, r2, r3, r4, r5, r6, r7;
                    bool ok;
                    do {
                        r0 = ld_vol4(row + 0 * 32 + lane);
                        r1 = ld_vol4(row + 1 * 32 + lane);
                        r2 = ld_vol4(row + 2 * 32 + lane);
                        r3 = ld_vol4(row + 3 * 32 + lane);
                        r4 = ld_vol4(row + 4 * 32 + lane);
                        r5 = ld_vol4(row + 5 * 32 + lane);
                        r6 = ld_vol4(row + 6 * 32 + lane);
                        r7 = ld_vol4(row + 7 * 32 + lane);
                        ok = ok4(r0) & ok4(r1) & ok4(r2) & ok4(r3)
                           & ok4(r4) & ok4(r5) & ok4(r6) & ok4(r7);
                    } while (!__all_sync(0xffffffffu, ok));
                    float4* d = (float4*)sH1b;
                    d[0 * 32 + lane] = r0; d[1 * 32 + lane] = r1;
                    d[2 * 32 + lane] = r2; d[3 * 32 + lane] = r3;
                    d[4 * 32 + lane] = r4; d[5 * 32 + lane] = r5;
                    d[6 * 32 + lane] = r6; d[7 * 32 + lane] = r7;
                }
            }
            asm volatile("bar.sync 2, 256;" ::: "memory");
            // stage h0[e] (proven visible via mailbox); volatile read from L2
            ((float4*)sH0b)[tb] = ld_vol4((const float4*)(H0 + (size_t)e * kNH) + tb);
            asm volatile("bar.sync 2, 256;" ::: "memory");

            // z1 = W_ih1 @ h0[e] + W_hh1 @ h1[e-1], 4 rows/warp
            const float2* h0p = (const float2*)sH0b;
            const float2* h1p = (const float2*)sH1b;
            float s0 = 0.f, s1 = 0.f, s2 = 0.f, s3 = 0.f;
#pragma unroll
            for (int j = 0; j < 16; j++) {
                const int idx = j * 32 + lane;
                float2 hv = h0p[idx];
                float2 w0 = __half22float2(wIh[idx]);
                float2 w1 = __half22float2(wIh[512 + idx]);
                float2 w2 = __half22float2(wIh[1024 + idx]);
                float2 w3 = __half22float2(wIh[1536 + idx]);
                s0 = fmaf(w0.x, hv.x, fmaf(w0.y, hv.y, s0));
                s1 = fmaf(w1.x, hv.x, fmaf(w1.y, hv.y, s1));
                s2 = fmaf(w2.x, hv.x, fmaf(w2.y, hv.y, s2));
                s3 = fmaf(w3.x, hv.x, fmaf(w3.y, hv.y, s3));
            }
#pragma unroll
            for (int j = 0; j < 16; j++) {
                const int idx = j * 32 + lane;
                float2 hv = h1p[idx];
                float2 w0 = __half22float2(wHh[idx]);
                float2 w1 = __half22float2(wHh[512 + idx]);
                float2 w2 = __half22float2(wHh[1024 + idx]);
                float2 w3 = __half22float2(wHh[1536 + idx]);
                s0 = fmaf(w0.x, hv.x, fmaf(w0.y, hv.y, s0));
                s1 = fmaf(w1.x, hv.x, fmaf(w1.y, hv.y, s1));
                s2 = fmaf(w2.x, hv.x, fmaf(w2.y, hv.y, s2));
                s3 = fmaf(w3.x, hv.x, fmaf(w3.y, hv.y, s3));
            }
#pragma unroll
            for (int off = 16; off; off >>= 1) {
                s0 += __shfl_xor_sync(0xffffffffu, s0, off);
                s1 += __shfl_xor_sync(0xffffffffu, s1, off);
                s2 += __shfl_xor_sync(0xffffffffu, s2, off);
                s3 += __shfl_xor_sync(0xffffffffu, s3, off);
            }
            if (lane == 0) {
                float* d = &sDotB[e & 1][wb * 4];
                d[0] = s0; d[1] = s1; d[2] = s2; d[3] = s3;
            }
            asm volatile("bar.sync 2, 256;" ::: "memory");

            if (warp == 7) {
                float z = sDotB[e & 1][lane] + bias;
                const bool isg = (lane >= 16) & (lane < 24);
                const float sm = isg ? 2.f : 1.f;
                float sig = 1.f / (1.f + __expf(-sm * z));
                float a = isg ? fmaf(sig, 2.f, -1.f) : sig;
                const int u = lane & 7;
                float i_ = __shfl_sync(0xffffffffu, a, u);
                float f_ = __shfl_sync(0xffffffffu, a, 8 + u);
                float g_ = __shfl_sync(0xffffffffu, a, 16 + u);
                float o_ = __shfl_sync(0xffffffffu, a, 24 + u);
                if (lane < kUnitsPerCTA) {
                    creg = fmaf(f_, creg, i_ * g_);
                    float tc = 2.f / (1.f + __expf(-2.f * creg)) - 1.f;
                    st_vol(H1 + (size_t)e * kNH + b * kUnitsPerCTA + lane, o_ * tc);
                }
            }
        }
    }
}

// ---------------- softmax over NO=512 per row ----------------
__global__ __launch_bounds__(256) void softmax_rows(
    const float* __restrict__ L, float* __restrict__ out)
{
    __shared__ float red[256];
    int t = blockIdx.x, tid = threadIdx.x;
    const float* row = L + (size_t)t * kNO;
    float v0 = row[tid], v1 = row[tid + 256];
    float m = fmaxf(v0, v1);
    red[tid] = m; __syncthreads();
    for (int s = 128; s; s >>= 1) {
        if (tid < s) red[tid] = fmaxf(red[tid], red[tid + s]);
        __syncthreads();
    }
    m = red[0]; __syncthreads();
    float e0 = expf(v0 - m), e1 = expf(v1 - m);
    red[tid] = e0 + e1; __syncthreads();
    for (int s = 128; s; s >>= 1) {
        if (tid < s) red[tid] += red[tid + s];
        __syncthreads();
    }
    float inv = 1.f / red[0];
    out[(size_t)t * kNO + tid]       = e0 * inv;
    out[(size_t)t * kNO + tid + 256] = e1 * inv;
}

// ---------------- value head: out[t] = H1[t] . w_val + b_val ----------------
__global__ __launch_bounds__(256) void value_head(
    const float* __restrict__ H1, const float* __restrict__ wv,
    const float* __restrict__ bv, float* __restrict__ out)
{
    __shared__ float red[256];
    int t = blockIdx.x, tid = threadIdx.x;
    const float* h = H1 + (size_t)t * kNH;
    float s = 0.f;
    for (int k = tid; k < kNH; k += 256) s += h[k] * wv[k];
    red[tid] = s; __syncthreads();
    for (int r = 128; r; r >>= 1) {
        if (tid < r) red[tid] += red[tid + r];
        __syncthreads();
    }
    if (tid == 0) out[t] = red[0] + bv[0];
}

// ---------------- launch ----------------
extern "C" void kernel_launch(void* const* d_in, const int* in_sizes, int n_in,
                              void* d_out, int out_size)
{
    (void)in_sizes; (void)n_in; (void)out_size;
    const float* x     = (const float*)d_in[0];
    const float* w_ih0 = (const float*)d_in[1];
    const float* w_hh0 = (const float*)d_in[2];
    const float* b_ih0 = (const float*)d_in[3];
    const float* b_hh0 = (const float*)d_in[4];
    const float* w_ih1 = (const float*)d_in[5];
    const float* w_hh1 = (const float*)d_in[6];
    const float* b_ih1 = (const float*)d_in[7];
    const float* b_hh1 = (const float*)d_in[8];
    const float* w_pol = (const float*)d_in[9];
    const float* b_pol = (const float*)d_in[10];
    const float* w_val = (const float*)d_in[11];
    const float* b_val = (const float*)d_in[12];
    float* out = (float*)d_out;

    float *Z, *H0, *H1;
    cudaGetSymbolAddress((void**)&Z, g_Z);
    cudaGetSymbolAddress((void**)&H0, g_H0);
    cudaGetSymbolAddress((void**)&H1, g_H1);

    const int smem = 3 * 32 * 512 * (int)sizeof(__half2);  // 192 KB dynamic (weights)
    cudaFuncSetAttribute(lstm_fused, cudaFuncAttributeMaxDynamicSharedMemorySize, smem);

    // NaN-canary prefill of H0/H1 (data-as-signal; replay-deterministic)
    const int n4 = kT * kNH / 4;  // 2M float4 per array
    prefill_nan<<<(n4 + 255) / 256, 256>>>((float4*)H0, n4);
    prefill_nan<<<(n4 + 255) / 256, 256>>>((float4*)H1, n4);

    // Z0 = X @ w_ih0^T + (b_ih0 + b_hh0)
    gemm_nt<<<dim3(kNG / 128, kT / 128), 256>>>(x, w_ih0, b_ih0, b_hh0, Z, kT, kNG, kNS);
    // fused 2-layer recurrence -> H0, H1
    lstm_fused<<<kNumCTA, 512, smem>>>(Z, w_hh0, w_ih1, w_hh1, b_ih1, b_hh1, H0, H1);
    // policy logits = H1 @ w_pol^T + b_pol (into Z scratch)
    gemm_nt<<<dim3(kNO / 128, kT / 128), 256>>>(H1, w_pol, b_pol, nullptr, Z, kT, kNO, kNH);
    // softmax -> out[0 : T*NO)
    softmax_rows<<<kT, 256>>>(Z, out);
    // value -> out[T*NO : T*NO + T)
    value_head<<<kT, 256>>>(H1, w_val, b_val, out + (size_t)kT * kNO);
}

// round 13
// speedup vs baseline: 8.8186x; 1.0382x over previous
#include <cuda_runtime.h>
#include <cuda_fp16.h>
#include <cstdint>

// Problem dims
constexpr int kT  = 8192;
constexpr int kNS = 512;
constexpr int kNH = 1024;
constexpr int kNO = 512;
constexpr int kNG = 4 * kNH;  // 4096 gate rows

constexpr int kNumCTA = 128;                 // persistent CTAs (<148 SMs -> co-resident)
constexpr int kUnitsPerCTA = kNH / kNumCTA;  // 8 hidden units per CTA

// ---------------- scratch (static device allocations; no cudaMalloc) ----------------
__device__ float g_Z[(size_t)kT * kNG];    // 128 MB: layer-0 gate preactivations / logits
__device__ float g_H0[(size_t)kT * kNH];   // 32 MB (NaN-canary protocol)
__device__ float g_H1[(size_t)kT * kNH];   // 32 MB (NaN-canary protocol)

// ---------------- NaN prefill: data-as-signal canary ----------------
__global__ void prefill_nan(float4* a, int n4) {
    int i = blockIdx.x * blockDim.x + threadIdx.x;
    const float qn = __int_as_float(0x7FC00000);
    float4 v = make_float4(qn, qn, qn, qn);
    if (i < n4) a[i] = v;
}

// ---------------- fp32 tiled GEMM: C[M,N] = A[M,K] * B[N,K]^T (+bias1[n]+bias2[n]) ----
__global__ __launch_bounds__(256) void gemm_nt(
    const float* __restrict__ A, const float* __restrict__ B,
    const float* __restrict__ b1, const float* __restrict__ b2,
    float* __restrict__ C, int M, int N, int K)
{
    __shared__ float As[8][128];
    __shared__ float Bs[8][128];
    const int tid = threadIdx.x;
    const int m0 = blockIdx.y * 128;
    const int n0 = blockIdx.x * 128;
    const int ty = tid >> 4;
    const int tx = tid & 15;
    const int lrow = tid >> 1;
    const int lk = (tid & 1) * 4;
    const float* Ap = A + (size_t)(m0 + lrow) * K + lk;
    const float* Bp = B + (size_t)(n0 + lrow) * K + lk;

    float acc[8][8];
#pragma unroll
    for (int i = 0; i < 8; i++)
#pragma unroll
        for (int j = 0; j < 8; j++) acc[i][j] = 0.f;

    for (int k0 = 0; k0 < K; k0 += 8) {
        float4 av = *(const float4*)(Ap + k0);
        float4 bv = *(const float4*)(Bp + k0);
        As[lk + 0][lrow] = av.x; As[lk + 1][lrow] = av.y;
        As[lk + 2][lrow] = av.z; As[lk + 3][lrow] = av.w;
        Bs[lk + 0][lrow] = bv.x; Bs[lk + 1][lrow] = bv.y;
        Bs[lk + 2][lrow] = bv.z; Bs[lk + 3][lrow] = bv.w;
        __syncthreads();
#pragma unroll
        for (int kk = 0; kk < 8; kk++) {
            float a[8], b[8];
#pragma unroll
            for (int i = 0; i < 8; i++) a[i] = As[kk][i * 16 + ty];
#pragma unroll
            for (int j = 0; j < 8; j++) b[j] = Bs[kk][j * 16 + tx];
#pragma unroll
            for (int i = 0; i < 8; i++)
#pragma unroll
                for (int j = 0; j < 8; j++) acc[i][j] += a[i] * b[j];
        }
        __syncthreads();
    }

#pragma unroll
    for (int j = 0; j < 8; j++) {
        int n = n0 + j * 16 + tx;
        float bias = 0.f;
        if (b1) bias += b1[n];
        if (b2) bias += b2[n];
#pragma unroll
        for (int i = 0; i < 8; i++) {
            int m = m0 + i * 16 + ty;
            C[(size_t)m * N + n] = acc[i][j] + bias;
        }
    }
}

// ---- helpers: volatile data-as-signal loads/stores ----
__device__ __forceinline__ float4 ld_vol4(const float4* p) {
    float4 v;
    asm volatile("ld.volatile.global.v4.f32 {%0,%1,%2,%3}, [%4];"
                 : "=f"(v.x), "=f"(v.y), "=f"(v.z), "=f"(v.w) : "l"(p) : "memory");
    return v;
}
__device__ __forceinline__ void st_vol(float* p, float v) {
    asm volatile("st.volatile.global.f32 [%0], %1;" :: "l"(p), "f"(v) : "memory");
}
__device__ __forceinline__ bool ok4(float4 v) {
    return (v.x == v.x) & (v.y == v.y) & (v.z == v.z) & (v.w == v.w);
}

// ---------------- fused 2-layer persistent LSTM recurrence -------------------------
// group A (warps 8-15, critical warp 15): layer 0, W_hh0 panel in REGISTERS
// group B (warps 0-7,  special  warp 7):  layer 1, W_ih1 in REGISTERS, W_hh1 in SMEM
// NaN-canary protocol for cross-CTA handoff (see R11).
__global__ __launch_bounds__(512) void lstm_fused(
    const float* __restrict__ Z0, const float* __restrict__ Whh0,
    const float* __restrict__ Wih1, const float* __restrict__ Whh1,
    const float* __restrict__ b_ih1, const float* __restrict__ b_hh1,
    float* H0, float* H1)
{
    extern __shared__ __half2 sW1h[];            // [32][512] half2 = 64 KB (W_hh1 only)
    __shared__ float sH0a[kNH];
    __shared__ float sH0b[kNH];
    __shared__ float sH1b[kNH];
    __shared__ float sDotA[2][32];
    __shared__ float sDotB[2][32];
    __shared__ float sBias1[32];
    __shared__ int   sSeen;                      // mailbox: sSeen = e  <=>  h0[e-1] proven

    const int tid  = threadIdx.x;
    const int b    = blockIdx.x;
    const int warp = tid >> 5;
    const int lane = tid & 31;
    const uint32_t seenAddr = (uint32_t)__cvta_generic_to_shared(&sSeen);

    // ---- load + convert W_hh1 panel into SMEM (gate-major lr = g*8+u) ----
    for (int i = tid; i < 32 * 512; i += 512) {
        int lr = i >> 9, p = i & 511;
        int g = lr >> 3, u = lr & 7;
        const float2 wv = *(const float2*)(
            Whh1 + (size_t)(g * kNH + b * kUnitsPerCTA + u) * kNH + 2 * p);
        sW1h[i] = __floats2half2_rn(wv.x, wv.y);
    }
    if (tid < 32) {
        int g = tid >> 3, u = tid & 7;
        int idx = g * kNH + b * kUnitsPerCTA + u;
        sBias1[tid] = b_ih1[idx] + b_hh1[idx];
    }
    if (tid < 256) {
        ((float4*)sH0a)[tid] = make_float4(0.f, 0.f, 0.f, 0.f);
        ((float4*)sH1b)[tid] = make_float4(0.f, 0.f, 0.f, 0.f);
    }
    if (tid == 0) sSeen = 0;
    __syncthreads();   // last whole-CTA barrier

    if (warp >= 8) {
        // ================= group A: layer 0 (warps 8-15) =================
        const int wa = warp - 8;
        float creg = 0.f;

        // register-resident W_hh0 panel: wreg[r][j] = row (wa*4+r), half2 #(j*32+lane)
        __half2 wreg[4][16];
#pragma unroll
        for (int r = 0; r < 4; r++) {
            const int lr = wa * 4 + r;
            const int g = lr >> 3, u = lr & 7;
            const float2* src = (const float2*)(
                Whh0 + (size_t)(g * kNH + b * kUnitsPerCTA + u) * kNH);
#pragma unroll
            for (int j = 0; j < 16; j++) {
                float2 w = src[j * 32 + lane];
                wreg[r][j] = __floats2half2_rn(w.x, w.y);
            }
        }

        for (int e = 0; e < kT; e++) {
            float zv = 0.f;
            if (warp == 15)
                zv = Z0[(size_t)e * kNG + (lane >> 3) * kNH + b * kUnitsPerCTA + (lane & 7)];

            if (e > 0) {
                if (warp == 15) {
                    // fused discovery+stage: poll the h0[e-1] DATA itself
                    const float4* row = (const float4*)(H0 + (size_t)(e - 1) * kNH);
                    float4 r0, r1, r2, r3, r4, r5, r6, r7;
                    bool ok;
                    do {
                        r0 = ld_vol4(row + 0 * 32 + lane);
                        r1 = ld_vol4(row + 1 * 32 + lane);
                        r2 = ld_vol4(row + 2 * 32 + lane);
                        r3 = ld_vol4(row + 3 * 32 + lane);
                        r4 = ld_vol4(row + 4 * 32 + lane);
                        r5 = ld_vol4(row + 5 * 32 + lane);
                        r6 = ld_vol4(row + 6 * 32 + lane);
                        r7 = ld_vol4(row + 7 * 32 + lane);
                        ok = ok4(r0) & ok4(r1) & ok4(r2) & ok4(r3)
                           & ok4(r4) & ok4(r5) & ok4(r6) & ok4(r7);
                    } while (!__all_sync(0xffffffffu, ok));
                    float4* d = (float4*)sH0a;
                    d[0 * 32 + lane] = r0; d[1 * 32 + lane] = r1;
                    d[2 * 32 + lane] = r2; d[3 * 32 + lane] = r3;
                    d[4 * 32 + lane] = r4; d[5 * 32 + lane] = r5;
                    d[6 * 32 + lane] = r6; d[7 * 32 + lane] = r7;
                    if (lane == 0)
                        asm volatile("st.release.cta.shared.u32 [%0], %1;"
                                     :: "r"(seenAddr), "r"(e) : "memory");
                }
                asm volatile("bar.sync 1, 256;" ::: "memory");   // sH0a ready
            }

            // matvec: 4 rows/warp, weights from registers, h from SMEM
            const float2* sHp = (const float2*)sH0a;
            float s0 = 0.f, s1 = 0.f, s2 = 0.f, s3 = 0.f;
#pragma unroll
            for (int j = 0; j < 16; j++) {
                float2 hv = sHp[j * 32 + lane];
                float2 w0 = __half22float2(wreg[0][j]);
                float2 w1 = __half22float2(wreg[1][j]);
                float2 w2 = __half22float2(wreg[2][j]);
                float2 w3 = __half22float2(wreg[3][j]);
                s0 = fmaf(w0.x, hv.x, fmaf(w0.y, hv.y, s0));
                s1 = fmaf(w1.x, hv.x, fmaf(w1.y, hv.y, s1));
                s2 = fmaf(w2.x, hv.x, fmaf(w2.y, hv.y, s2));
                s3 = fmaf(w3.x, hv.x, fmaf(w3.y, hv.y, s3));
            }
#pragma unroll
            for (int off = 16; off; off >>= 1) {
                s0 += __shfl_xor_sync(0xffffffffu, s0, off);
                s1 += __shfl_xor_sync(0xffffffffu, s1, off);
                s2 += __shfl_xor_sync(0xffffffffu, s2, off);
                s3 += __shfl_xor_sync(0xffffffffu, s3, off);
            }
            if (lane == 0) {
                float* d = &sDotA[e & 1][wa * 4];
                d[0] = s0; d[1] = s1; d[2] = s2; d[3] = s3;
            }
            asm volatile("bar.sync 1, 256;" ::: "memory");

            if (warp == 15) {
                float z = sDotA[e & 1][lane] + zv;
                const bool isg = (lane >= 16) & (lane < 24);
                const float sm = isg ? 2.f : 1.f;
                float sig = 1.f / (1.f + __expf(-sm * z));
                float a = isg ? fmaf(sig, 2.f, -1.f) : sig;
                const int u = lane & 7;
                float i_ = __shfl_sync(0xffffffffu, a, u);
                float f_ = __shfl_sync(0xffffffffu, a, 8 + u);
                float g_ = __shfl_sync(0xffffffffu, a, 16 + u);
                float o_ = __shfl_sync(0xffffffffu, a, 24 + u);
                if (lane < kUnitsPerCTA) {
                    creg = fmaf(f_, creg, i_ * g_);
                    float tc = 2.f / (1.f + __expf(-2.f * creg)) - 1.f;
                    st_vol(H0 + (size_t)e * kNH + b * kUnitsPerCTA + lane, o_ * tc);
                }
            }
        }
        // post-loop: prove h0[kT-1] complete so B's last epoch can proceed
        if (warp == 15) {
            const float4* row = (const float4*)(H0 + (size_t)(kT - 1) * kNH);
            bool ok;
            do {
                ok = true;
#pragma unroll
                for (int i = 0; i < 8; i++) ok &= ok4(ld_vol4(row + i * 32 + lane));
            } while (!__all_sync(0xffffffffu, ok));
            if (lane == 0)
                asm volatile("st.release.cta.shared.u32 [%0], %1;"
                             :: "r"(seenAddr), "r"(kT) : "memory");
        }
    } else {
        // ================= group B: layer 1 (warps 0-7) =================
        const int wb = warp;
        const int tb = tid;                            // 0..255 within group
        const __half2* wHh = sW1h + (size_t)(wb * 4) * 512;
        float creg = 0.f;
        const float bias = sBias1[lane];

        // register-resident W_ih1 panel
        __half2 wreg[4][16];
#pragma unroll
        for (int r = 0; r < 4; r++) {
            const int lr = wb * 4 + r;
            const int g = lr >> 3, u = lr & 7;
            const float2* src = (const float2*)(
                Wih1 + (size_t)(g * kNH + b * kUnitsPerCTA + u) * kNH);
#pragma unroll
            for (int j = 0; j < 16; j++) {
                float2 w = src[j * 32 + lane];
                wreg[r][j] = __floats2half2_rn(w.x, w.y);
            }
        }

        for (int e = 0; e < kT; e++) {
            if (warp == 7) {
                // layer-0 dep: mailbox (sSeen >= e+1  <=>  h0[e] proven visible)
                int sv;
                do {
                    asm volatile("ld.acquire.cta.shared.u32 %0, [%1];"
                                 : "=r"(sv) : "r"(seenAddr) : "memory");
                } while (sv < e + 1);
                // layer-1 dep: NaN-poll h1[e-1] data, fused with staging
                if (e > 0) {
                    const float4* row = (const float4*)(H1 + (size_t)(e - 1) * kNH);
                    float4 r0, r1, r2, r3, r4, r5, r6, r7;
                    bool ok;
                    do {
                        r0 = ld_vol4(row + 0 * 32 + lane);
                        r1 = ld_vol4(row + 1 * 32 + lane);
                        r2 = ld_vol4(row + 2 * 32 + lane);
                        r3 = ld_vol4(row + 3 * 32 + lane);
                        r4 = ld_vol4(row + 4 * 32 + lane);
                        r5 = ld_vol4(row + 5 * 32 + lane);
                        r6 = ld_vol4(row + 6 * 32 + lane);
                        r7 = ld_vol4(row + 7 * 32 + lane);
                        ok = ok4(r0) & ok4(r1) & ok4(r2) & ok4(r3)
                           & ok4(r4) & ok4(r5) & ok4(r6) & ok4(r7);
                    } while (!__all_sync(0xffffffffu, ok));
                    float4* d = (float4*)sH1b;
                    d[0 * 32 + lane] = r0; d[1 * 32 + lane] = r1;
                    d[2 * 32 + lane] = r2; d[3 * 32 + lane] = r3;
                    d[4 * 32 + lane] = r4; d[5 * 32 + lane] = r5;
                    d[6 * 32 + lane] = r6; d[7 * 32 + lane] = r7;
                }
            }
            asm volatile("bar.sync 2, 256;" ::: "memory");
            // stage h0[e] (proven visible via mailbox)
            ((float4*)sH0b)[tb] = ld_vol4((const float4*)(H0 + (size_t)e * kNH) + tb);
            asm volatile("bar.sync 2, 256;" ::: "memory");

            // z1 = W_ih1(regs) @ h0[e] + W_hh1(SMEM) @ h1[e-1], 4 rows/warp
            const float2* h0p = (const float2*)sH0b;
            const float2* h1p = (const float2*)sH1b;
            float s0 = 0.f, s1 = 0.f, s2 = 0.f, s3 = 0.f;
#pragma unroll
            for (int j = 0; j < 16; j++) {
                float2 hv = h0p[j * 32 + lane];
                float2 w0 = __half22float2(wreg[0][j]);
                float2 w1 = __half22float2(wreg[1][j]);
                float2 w2 = __half22float2(wreg[2][j]);
                float2 w3 = __half22float2(wreg[3][j]);
                s0 = fmaf(w0.x, hv.x, fmaf(w0.y, hv.y, s0));
                s1 = fmaf(w1.x, hv.x, fmaf(w1.y, hv.y, s1));
                s2 = fmaf(w2.x, hv.x, fmaf(w2.y, hv.y, s2));
                s3 = fmaf(w3.x, hv.x, fmaf(w3.y, hv.y, s3));
            }
#pragma unroll
            for (int j = 0; j < 16; j++) {
                const int idx = j * 32 + lane;
                float2 hv = h1p[idx];
                float2 w0 = __half22float2(wHh[idx]);
                float2 w1 = __half22float2(wHh[512 + idx]);
                float2 w2 = __half22float2(wHh[1024 + idx]);
                float2 w3 = __half22float2(wHh[1536 + idx]);
                s0 = fmaf(w0.x, hv.x, fmaf(w0.y, hv.y, s0));
                s1 = fmaf(w1.x, hv.x, fmaf(w1.y, hv.y, s1));
                s2 = fmaf(w2.x, hv.x, fmaf(w2.y, hv.y, s2));
                s3 = fmaf(w3.x, hv.x, fmaf(w3.y, hv.y, s3));
            }
#pragma unroll
            for (int off = 16; off; off >>= 1) {
                s0 += __shfl_xor_sync(0xffffffffu, s0, off);
                s1 += __shfl_xor_sync(0xffffffffu, s1, off);
                s2 += __shfl_xor_sync(0xffffffffu, s2, off);
                s3 += __shfl_xor_sync(0xffffffffu, s3, off);
            }
            if (lane == 0) {
                float* d = &sDotB[e & 1][wb * 4];
                d[0] = s0; d[1] = s1; d[2] = s2; d[3] = s3;
            }
            asm volatile("bar.sync 2, 256;" ::: "memory");

            if (warp == 7) {
                float z = sDotB[e & 1][lane] + bias;
                const bool isg = (lane >= 16) & (lane < 24);
                const float sm = isg ? 2.f : 1.f;
                float sig = 1.f / (1.f + __expf(-sm * z));
                float a = isg ? fmaf(sig, 2.f, -1.f) : sig;
                const int u = lane & 7;
                float i_ = __shfl_sync(0xffffffffu, a, u);
                float f_ = __shfl_sync(0xffffffffu, a, 8 + u);
                float g_ = __shfl_sync(0xffffffffu, a, 16 + u);
                float o_ = __shfl_sync(0xffffffffu, a, 24 + u);
                if (lane < kUnitsPerCTA) {
                    creg = fmaf(f_, creg, i_ * g_);
                    float tc = 2.f / (1.f + __expf(-2.f * creg)) - 1.f;
                    st_vol(H1 + (size_t)e * kNH + b * kUnitsPerCTA + lane, o_ * tc);
                }
            }
        }
    }
}

// ---------------- softmax over NO=512 per row ----------------
__global__ __launch_bounds__(256) void softmax_rows(
    const float* __restrict__ L, float* __restrict__ out)
{
    __shared__ float red[256];
    int t = blockIdx.x, tid = threadIdx.x;
    const float* row = L + (size_t)t * kNO;
    float v0 = row[tid], v1 = row[tid + 256];
    float m = fmaxf(v0, v1);
    red[tid] = m; __syncthreads();
    for (int s = 128; s; s >>= 1) {
        if (tid < s) red[tid] = fmaxf(red[tid], red[tid + s]);
        __syncthreads();
    }
    m = red[0]; __syncthreads();
    float e0 = expf(v0 - m), e1 = expf(v1 - m);
    red[tid] = e0 + e1; __syncthreads();
    for (int s = 128; s; s >>= 1) {
        if (tid < s) red[tid] += red[tid + s];
        __syncthreads();
    }
    float inv = 1.f / red[0];
    out[(size_t)t * kNO + tid]       = e0 * inv;
    out[(size_t)t * kNO + tid + 256] = e1 * inv;
}

// ---------------- value head: out[t] = H1[t] . w_val + b_val ----------------
__global__ __launch_bounds__(256) void value_head(
    const float* __restrict__ H1, const float* __restrict__ wv,
    const float* __restrict__ bv, float* __restrict__ out)
{
    __shared__ float red[256];
    int t = blockIdx.x, tid = threadIdx.x;
    const float* h = H1 + (size_t)t * kNH;
    float s = 0.f;
    for (int k = tid; k < kNH; k += 256) s += h[k] * wv[k];
    red[tid] = s; __syncthreads();
    for (int r = 128; r; r >>= 1) {
        if (tid < r) red[tid] += red[tid + r];
        __syncthreads();
    }
    if (tid == 0) out[t] = red[0] + bv[0];
}

// ---------------- launch ----------------
extern "C" void kernel_launch(void* const* d_in, const int* in_sizes, int n_in,
                              void* d_out, int out_size)
{
    (void)in_sizes; (void)n_in; (void)out_size;
    const float* x     = (const float*)d_in[0];
    const float* w_ih0 = (const float*)d_in[1];
    const float* w_hh0 = (const float*)d_in[2];
    const float* b_ih0 = (const float*)d_in[3];
    const float* b_hh0 = (const float*)d_in[4];
    const float* w_ih1 = (const float*)d_in[5];
    const float* w_hh1 = (const float*)d_in[6];
    const float* b_ih1 = (const float*)d_in[7];
    const float* b_hh1 = (const float*)d_in[8];
    const float* w_pol = (const float*)d_in[9];
    const float* b_pol = (const float*)d_in[10];
    const float* w_val = (const float*)d_in[11];
    const float* b_val = (const float*)d_in[12];
    float* out = (float*)d_out;

    float *Z, *H0, *H1;
    cudaGetSymbolAddress((void**)&Z, g_Z);
    cudaGetSymbolAddress((void**)&H0, g_H0);
    cudaGetSymbolAddress((void**)&H1, g_H1);

    const int smem = 32 * 512 * (int)sizeof(__half2);  // 64 KB dynamic (W_hh1 only)
    cudaFuncSetAttribute(lstm_fused, cudaFuncAttributeMaxDynamicSharedMemorySize, smem);

    // NaN-canary prefill of H0/H1 (data-as-signal; replay-deterministic)
    const int n4 = kT * kNH / 4;  // 2M float4 per array
    prefill_nan<<<(n4 + 255) / 256, 256>>>((float4*)H0, n4);
    prefill_nan<<<(n4 + 255) / 256, 256>>>((float4*)H1, n4);

    // Z0 = X @ w_ih0^T + (b_ih0 + b_hh0)
    gemm_nt<<<dim3(kNG / 128, kT / 128), 256>>>(x, w_ih0, b_ih0, b_hh0, Z, kT, kNG, kNS);
    // fused 2-layer recurrence -> H0, H1
    lstm_fused<<<kNumCTA, 512, smem>>>(Z, w_hh0, w_ih1, w_hh1, b_ih1, b_hh1, H0, H1);
    // policy logits = H1 @ w_pol^T + b_pol (into Z scratch)
    gemm_nt<<<dim3(kNO / 128, kT / 128), 256>>>(H1, w_pol, b_pol, nullptr, Z, kT, kNO, kNH);
    // softmax -> out[0 : T*NO)
    softmax_rows<<<kT, 256>>>(Z, out);
    // value -> out[T*NO : T*NO + T)
    value_head<<<kT, 256>>>(H1, w_val, b_val, out + (size_t)kT * kNO);
}